// round 1
// baseline (speedup 1.0000x reference)
#include <cuda_runtime.h>
#include <cuda_bf16.h>
#include <math.h>

#define BB 4
#define SS 2048
#define DD 1024
#define HH 16
#define HDIM 64

// Scratch (device globals: allocation-free per harness rules)
__device__ float g_qkv[BB * SS * 3 * DD];   // [B,S,3D]
__device__ float g_ctx[BB * SS * DD];       // [B,S,D] (heads already merged)

// ---------------------------------------------------------------------------
// GEMM: C[M,N] = A[M,K] @ W[K,N] + bias[N]
// Block tile 64x64, K-tile 16, 256 threads, 4x4 microtile per thread.
// ---------------------------------------------------------------------------
__global__ __launch_bounds__(256)
void gemm_bias_kernel(const float* __restrict__ A,
                      const float* __restrict__ W,
                      const float* __restrict__ bias,
                      float* __restrict__ C,
                      int M, int N, int K)
{
    __shared__ float As[16][64];   // transposed: As[k][m]
    __shared__ float Ws[16][64];   // Ws[k][n]

    const int tid = threadIdx.x;
    const int tx = tid % 16;       // micro col group
    const int ty = tid / 16;       // micro row group
    const int row0 = blockIdx.y * 64;
    const int col0 = blockIdx.x * 64;

    float acc[4][4] = {};

    for (int k0 = 0; k0 < K; k0 += 16) {
        // Load A tile 64x16 (each thread one float4 along K)
        {
            int r = tid >> 2;            // 0..63
            int c = (tid & 3) * 4;       // 0,4,8,12
            float4 v = *reinterpret_cast<const float4*>(
                &A[(size_t)(row0 + r) * K + k0 + c]);
            As[c + 0][r] = v.x;
            As[c + 1][r] = v.y;
            As[c + 2][r] = v.z;
            As[c + 3][r] = v.w;
        }
        // Load W tile 16x64 (each thread one float4 along N)
        {
            int r = tid >> 4;            // 0..15
            int c = (tid & 15) * 4;      // 0..60
            float4 v = *reinterpret_cast<const float4*>(
                &W[(size_t)(k0 + r) * N + col0 + c]);
            *reinterpret_cast<float4*>(&Ws[r][c]) = v;
        }
        __syncthreads();

        #pragma unroll
        for (int k = 0; k < 16; k++) {
            float a[4], b[4];
            *reinterpret_cast<float4*>(a) =
                *reinterpret_cast<const float4*>(&As[k][ty * 4]);
            *reinterpret_cast<float4*>(b) =
                *reinterpret_cast<const float4*>(&Ws[k][tx * 4]);
            #pragma unroll
            for (int i = 0; i < 4; i++)
                #pragma unroll
                for (int j = 0; j < 4; j++)
                    acc[i][j] = fmaf(a[i], b[j], acc[i][j]);
        }
        __syncthreads();
    }

    #pragma unroll
    for (int i = 0; i < 4; i++) {
        int row = row0 + ty * 4 + i;
        #pragma unroll
        for (int j = 0; j < 4; j++) {
            int col = col0 + tx * 4 + j;
            C[(size_t)row * N + col] = acc[i][j] + bias[col];
        }
    }
}

// ---------------------------------------------------------------------------
// Causal flash attention.
// grid = (B*H, S/128); 128 threads, one thread per query row.
// q[64] and acc[64] in registers; K/V tiles (32 keys) in smem (broadcast LDS).
// ---------------------------------------------------------------------------
__global__ __launch_bounds__(128)
void attention_kernel(const float* __restrict__ qkv, float* __restrict__ ctx)
{
    const int bh = blockIdx.x;
    const int b  = bh / HH;
    const int h  = bh % HH;
    const int s_q = blockIdx.y * 128 + threadIdx.x;

    // Load this thread's query row into registers
    const float* qrow = qkv + ((size_t)(b * SS + s_q)) * (3 * DD) + h * HDIM;
    float q[HDIM];
    #pragma unroll
    for (int d = 0; d < HDIM; d += 4)
        *reinterpret_cast<float4*>(&q[d]) =
            *reinterpret_cast<const float4*>(&qrow[d]);

    const float scale = 0.125f;   // 1/sqrt(64)

    float acc[HDIM];
    #pragma unroll
    for (int d = 0; d < HDIM; d++) acc[d] = 0.f;
    float m = -1e30f, l = 0.f;

    __shared__ float Ks[32][HDIM];
    __shared__ float Vs[32][HDIM];

    const int kend = (blockIdx.y + 1) * 128;   // causal bound (exclusive)

    for (int k0 = 0; k0 < kend; k0 += 32) {
        // Cooperative load of K and V tiles: 32x64 floats each.
        // 512 float4 per tile / 128 threads = 4 float4 each.
        {
            const int t = threadIdx.x;
            #pragma unroll
            for (int i = 0; i < 4; i++) {
                int idx = t * 4 + i;          // 0..511
                int row = idx >> 4;           // 0..31
                int col = (idx & 15) * 4;     // 0..60
                const float* kp = qkv
                    + ((size_t)(b * SS + k0 + row)) * (3 * DD)
                    + DD + h * HDIM + col;
                *reinterpret_cast<float4*>(&Ks[row][col]) =
                    *reinterpret_cast<const float4*>(kp);
                *reinterpret_cast<float4*>(&Vs[row][col]) =
                    *reinterpret_cast<const float4*>(kp + DD);
            }
        }
        __syncthreads();

        // S = q . K^T  (masked), track tile max
        float sc[32];
        float tmax = -1e30f;
        #pragma unroll
        for (int j = 0; j < 32; j++) {
            float d0 = 0.f, d1 = 0.f, d2 = 0.f, d3 = 0.f;
            #pragma unroll
            for (int d = 0; d < HDIM; d += 4) {
                float4 kv = *reinterpret_cast<const float4*>(&Ks[j][d]);
                d0 = fmaf(q[d + 0], kv.x, d0);
                d1 = fmaf(q[d + 1], kv.y, d1);
                d2 = fmaf(q[d + 2], kv.z, d2);
                d3 = fmaf(q[d + 3], kv.w, d3);
            }
            float dot = (d0 + d1) + (d2 + d3);
            sc[j] = ((k0 + j) <= s_q) ? dot * scale : -1e30f;
            tmax = fmaxf(tmax, sc[j]);
        }

        // Online softmax rescale
        float m_new = fmaxf(m, tmax);
        float corr = __expf(m - m_new);
        l *= corr;
        #pragma unroll
        for (int d = 0; d < HDIM; d++) acc[d] *= corr;

        // P·V accumulate
        #pragma unroll
        for (int j = 0; j < 32; j++) {
            float p = __expf(sc[j] - m_new);
            l += p;
            #pragma unroll
            for (int d = 0; d < HDIM; d += 4) {
                float4 vv = *reinterpret_cast<const float4*>(&Vs[j][d]);
                acc[d + 0] = fmaf(p, vv.x, acc[d + 0]);
                acc[d + 1] = fmaf(p, vv.y, acc[d + 1]);
                acc[d + 2] = fmaf(p, vv.z, acc[d + 2]);
                acc[d + 3] = fmaf(p, vv.w, acc[d + 3]);
            }
        }
        m = m_new;
        __syncthreads();
    }

    // Normalize and write merged-head context
    const float inv_l = 1.f / l;
    float* out = ctx + ((size_t)(b * SS + s_q)) * DD + h * HDIM;
    #pragma unroll
    for (int d = 0; d < HDIM; d += 4) {
        float4 o;
        o.x = acc[d + 0] * inv_l;
        o.y = acc[d + 1] * inv_l;
        o.z = acc[d + 2] * inv_l;
        o.w = acc[d + 3] * inv_l;
        *reinterpret_cast<float4*>(&out[d]) = o;
    }
}

// ---------------------------------------------------------------------------
// Launch
// ---------------------------------------------------------------------------
extern "C" void kernel_launch(void* const* d_in, const int* in_sizes, int n_in,
                              void* d_out, int out_size)
{
    const float* hidden = (const float*)d_in[0];   // [B,S,D]
    const float* w_attn = (const float*)d_in[1];   // [D,3D]
    const float* b_attn = (const float*)d_in[2];   // [3D]
    const float* w_proj = (const float*)d_in[3];   // [D,D]
    const float* b_proj = (const float*)d_in[4];   // [D]
    float* out = (float*)d_out;                    // [B,S,D]

    float *qkv_ptr = nullptr, *ctx_ptr = nullptr;
    cudaGetSymbolAddress((void**)&qkv_ptr, g_qkv);
    cudaGetSymbolAddress((void**)&ctx_ptr, g_ctx);

    const int M = BB * SS;   // 8192

    // 1) QKV = hidden @ w_attn + b_attn      [8192, 3072]
    {
        dim3 grid(3 * DD / 64, M / 64);
        gemm_bias_kernel<<<grid, 256>>>(hidden, w_attn, b_attn, qkv_ptr,
                                        M, 3 * DD, DD);
    }

    // 2) ctx = causal_attention(q, k, v)     [8192, 1024] (heads merged)
    {
        dim3 grid(BB * HH, SS / 128);
        attention_kernel<<<grid, 128>>>(qkv_ptr, ctx_ptr);
    }

    // 3) out = ctx @ w_proj + b_proj         [8192, 1024]
    {
        dim3 grid(DD / 64, M / 64);
        gemm_bias_kernel<<<grid, 256>>>(ctx_ptr, w_proj, b_proj, out,
                                        M, DD, DD);
    }
}

// round 2
// speedup vs baseline: 1.5272x; 1.5272x over previous
#include <cuda_runtime.h>
#include <cuda_bf16.h>
#include <math.h>

#define BB 4
#define SS 2048
#define DD 1024
#define HH 16
#define HDIM 64

// Scratch (device globals: allocation-free per harness rules)
__device__ float g_qkv[BB * SS * 3 * DD];   // [B,S,3D]
__device__ float g_ctx[BB * SS * DD];       // [B,S,D] (heads already merged)

__device__ __forceinline__ unsigned f2tf32(float x) {
    unsigned r;
    asm("cvt.rna.tf32.f32 %0, %1;" : "=r"(r) : "f"(x));
    return r;
}

// ---------------------------------------------------------------------------
// TF32 tensor-core GEMM: C[M,N] = A[M,K] @ W[K,N] + bias[N]
// CTA tile 128x128, BK=16, 256 threads = 8 warps (4x2), warp tile 32x64.
// mma.sync.aligned.m16n8k8.row.col.f32.tf32.tf32.f32
// As stride 20 (a-frag LDS conflict-free), Bs stride 136 (b-frag conflict-free)
// ---------------------------------------------------------------------------
#define LDA_S 20
#define LDB_S 136

__global__ __launch_bounds__(256)
void gemm_tf32_kernel(const float* __restrict__ A,
                      const float* __restrict__ W,
                      const float* __restrict__ bias,
                      float* __restrict__ C,
                      int M, int N, int K)
{
    __shared__ float As[128 * LDA_S];
    __shared__ float Bs[16 * LDB_S];

    const int tid  = threadIdx.x;
    const int warp = tid >> 5;
    const int lane = tid & 31;
    const int gid  = lane >> 2;   // group id (0..7)
    const int tig  = lane & 3;    // thread in group

    const int wm = warp >> 1;     // 0..3 -> warp row tile (32 rows each)
    const int wn = warp & 1;      // 0..1 -> warp col tile (64 cols each)

    const int row0 = blockIdx.y * 128;
    const int col0 = blockIdx.x * 128;

    float acc[2][8][4];
    #pragma unroll
    for (int i = 0; i < 2; i++)
        #pragma unroll
        for (int j = 0; j < 8; j++)
            #pragma unroll
            for (int v = 0; v < 4; v++) acc[i][j][v] = 0.f;

    // loader indices
    const int ar = tid >> 1;             // 0..127 (A row within tile)
    const int ac = (tid & 1) * 8;        // 0 or 8
    const int br = tid >> 4;             // 0..15  (B row = k within tile)
    const int bc = (tid & 15) * 8;       // 0..120

    for (int k0 = 0; k0 < K; k0 += 16) {
        // ---- load A tile 128x16 (each thread: 8 contiguous floats of one row)
        {
            const float* ap = A + (size_t)(row0 + ar) * K + k0 + ac;
            float4 v0 = *reinterpret_cast<const float4*>(ap);
            float4 v1 = *reinterpret_cast<const float4*>(ap + 4);
            float* dst = &As[ar * LDA_S + ac];
            dst[0] = __uint_as_float(f2tf32(v0.x));
            dst[1] = __uint_as_float(f2tf32(v0.y));
            dst[2] = __uint_as_float(f2tf32(v0.z));
            dst[3] = __uint_as_float(f2tf32(v0.w));
            dst[4] = __uint_as_float(f2tf32(v1.x));
            dst[5] = __uint_as_float(f2tf32(v1.y));
            dst[6] = __uint_as_float(f2tf32(v1.z));
            dst[7] = __uint_as_float(f2tf32(v1.w));
        }
        // ---- load B tile 16x128
        {
            const float* wp = W + (size_t)(k0 + br) * N + col0 + bc;
            float4 v0 = *reinterpret_cast<const float4*>(wp);
            float4 v1 = *reinterpret_cast<const float4*>(wp + 4);
            float* dst = &Bs[br * LDB_S + bc];
            dst[0] = __uint_as_float(f2tf32(v0.x));
            dst[1] = __uint_as_float(f2tf32(v0.y));
            dst[2] = __uint_as_float(f2tf32(v0.z));
            dst[3] = __uint_as_float(f2tf32(v0.w));
            dst[4] = __uint_as_float(f2tf32(v1.x));
            dst[5] = __uint_as_float(f2tf32(v1.y));
            dst[6] = __uint_as_float(f2tf32(v1.z));
            dst[7] = __uint_as_float(f2tf32(v1.w));
        }
        __syncthreads();

        #pragma unroll
        for (int kk = 0; kk < 16; kk += 8) {
            // A fragments for the 2 m16 tiles of this warp
            unsigned afrag[2][4];
            #pragma unroll
            for (int mi = 0; mi < 2; mi++) {
                int r = wm * 32 + mi * 16 + gid;
                afrag[mi][0] = __float_as_uint(As[r * LDA_S + kk + tig]);
                afrag[mi][1] = __float_as_uint(As[(r + 8) * LDA_S + kk + tig]);
                afrag[mi][2] = __float_as_uint(As[r * LDA_S + kk + tig + 4]);
                afrag[mi][3] = __float_as_uint(As[(r + 8) * LDA_S + kk + tig + 4]);
            }
            #pragma unroll
            for (int ni = 0; ni < 8; ni++) {
                int c = wn * 64 + ni * 8 + gid;
                unsigned b0 = __float_as_uint(Bs[(kk + tig) * LDB_S + c]);
                unsigned b1 = __float_as_uint(Bs[(kk + tig + 4) * LDB_S + c]);
                #pragma unroll
                for (int mi = 0; mi < 2; mi++) {
                    asm volatile(
                        "mma.sync.aligned.m16n8k8.row.col.f32.tf32.tf32.f32 "
                        "{%0,%1,%2,%3}, {%4,%5,%6,%7}, {%8,%9}, {%0,%1,%2,%3};\n"
                        : "+f"(acc[mi][ni][0]), "+f"(acc[mi][ni][1]),
                          "+f"(acc[mi][ni][2]), "+f"(acc[mi][ni][3])
                        : "r"(afrag[mi][0]), "r"(afrag[mi][1]),
                          "r"(afrag[mi][2]), "r"(afrag[mi][3]),
                          "r"(b0), "r"(b1));
                }
            }
        }
        __syncthreads();
    }

    // epilogue: add bias, store
    #pragma unroll
    for (int mi = 0; mi < 2; mi++) {
        int r = row0 + wm * 32 + mi * 16 + gid;
        #pragma unroll
        for (int ni = 0; ni < 8; ni++) {
            int c = col0 + wn * 64 + ni * 8 + 2 * tig;
            float bx = __ldg(&bias[c]);
            float by = __ldg(&bias[c + 1]);
            float2 o0 = make_float2(acc[mi][ni][0] + bx, acc[mi][ni][1] + by);
            float2 o1 = make_float2(acc[mi][ni][2] + bx, acc[mi][ni][3] + by);
            *reinterpret_cast<float2*>(&C[(size_t)r * N + c]) = o0;
            *reinterpret_cast<float2*>(&C[(size_t)(r + 8) * N + c]) = o1;
        }
    }
}

// ---------------------------------------------------------------------------
// Causal flash attention (unchanged from R1 baseline).
// grid = (B*H, S/128); 128 threads, one thread per query row.
// ---------------------------------------------------------------------------
__global__ __launch_bounds__(128)
void attention_kernel(const float* __restrict__ qkv, float* __restrict__ ctx)
{
    const int bh = blockIdx.x;
    const int b  = bh / HH;
    const int h  = bh % HH;
    const int s_q = blockIdx.y * 128 + threadIdx.x;

    const float* qrow = qkv + ((size_t)(b * SS + s_q)) * (3 * DD) + h * HDIM;
    float q[HDIM];
    #pragma unroll
    for (int d = 0; d < HDIM; d += 4)
        *reinterpret_cast<float4*>(&q[d]) =
            *reinterpret_cast<const float4*>(&qrow[d]);

    const float scale = 0.125f;   // 1/sqrt(64)

    float acc[HDIM];
    #pragma unroll
    for (int d = 0; d < HDIM; d++) acc[d] = 0.f;
    float m = -1e30f, l = 0.f;

    __shared__ float Ks[32][HDIM];
    __shared__ float Vs[32][HDIM];

    const int kend = (blockIdx.y + 1) * 128;   // causal bound (exclusive)

    for (int k0 = 0; k0 < kend; k0 += 32) {
        {
            const int t = threadIdx.x;
            #pragma unroll
            for (int i = 0; i < 4; i++) {
                int idx = t * 4 + i;
                int row = idx >> 4;
                int col = (idx & 15) * 4;
                const float* kp = qkv
                    + ((size_t)(b * SS + k0 + row)) * (3 * DD)
                    + DD + h * HDIM + col;
                *reinterpret_cast<float4*>(&Ks[row][col]) =
                    *reinterpret_cast<const float4*>(kp);
                *reinterpret_cast<float4*>(&Vs[row][col]) =
                    *reinterpret_cast<const float4*>(kp + DD);
            }
        }
        __syncthreads();

        float sc[32];
        float tmax = -1e30f;
        #pragma unroll
        for (int j = 0; j < 32; j++) {
            float d0 = 0.f, d1 = 0.f, d2 = 0.f, d3 = 0.f;
            #pragma unroll
            for (int d = 0; d < HDIM; d += 4) {
                float4 kv = *reinterpret_cast<const float4*>(&Ks[j][d]);
                d0 = fmaf(q[d + 0], kv.x, d0);
                d1 = fmaf(q[d + 1], kv.y, d1);
                d2 = fmaf(q[d + 2], kv.z, d2);
                d3 = fmaf(q[d + 3], kv.w, d3);
            }
            float dot = (d0 + d1) + (d2 + d3);
            sc[j] = ((k0 + j) <= s_q) ? dot * scale : -1e30f;
            tmax = fmaxf(tmax, sc[j]);
        }

        float m_new = fmaxf(m, tmax);
        float corr = __expf(m - m_new);
        l *= corr;
        #pragma unroll
        for (int d = 0; d < HDIM; d++) acc[d] *= corr;

        #pragma unroll
        for (int j = 0; j < 32; j++) {
            float p = __expf(sc[j] - m_new);
            l += p;
            #pragma unroll
            for (int d = 0; d < HDIM; d += 4) {
                float4 vv = *reinterpret_cast<const float4*>(&Vs[j][d]);
                acc[d + 0] = fmaf(p, vv.x, acc[d + 0]);
                acc[d + 1] = fmaf(p, vv.y, acc[d + 1]);
                acc[d + 2] = fmaf(p, vv.z, acc[d + 2]);
                acc[d + 3] = fmaf(p, vv.w, acc[d + 3]);
            }
        }
        m = m_new;
        __syncthreads();
    }

    const float inv_l = 1.f / l;
    float* out = ctx + ((size_t)(b * SS + s_q)) * DD + h * HDIM;
    #pragma unroll
    for (int d = 0; d < HDIM; d += 4) {
        float4 o;
        o.x = acc[d + 0] * inv_l;
        o.y = acc[d + 1] * inv_l;
        o.z = acc[d + 2] * inv_l;
        o.w = acc[d + 3] * inv_l;
        *reinterpret_cast<float4*>(&out[d]) = o;
    }
}

// ---------------------------------------------------------------------------
// Launch
// ---------------------------------------------------------------------------
extern "C" void kernel_launch(void* const* d_in, const int* in_sizes, int n_in,
                              void* d_out, int out_size)
{
    const float* hidden = (const float*)d_in[0];   // [B,S,D]
    const float* w_attn = (const float*)d_in[1];   // [D,3D]
    const float* b_attn = (const float*)d_in[2];   // [3D]
    const float* w_proj = (const float*)d_in[3];   // [D,D]
    const float* b_proj = (const float*)d_in[4];   // [D]
    float* out = (float*)d_out;                    // [B,S,D]

    float *qkv_ptr = nullptr, *ctx_ptr = nullptr;
    cudaGetSymbolAddress((void**)&qkv_ptr, g_qkv);
    cudaGetSymbolAddress((void**)&ctx_ptr, g_ctx);

    const int M = BB * SS;   // 8192

    // 1) QKV = hidden @ w_attn + b_attn      [8192, 3072]
    {
        dim3 grid(3 * DD / 128, M / 128);
        gemm_tf32_kernel<<<grid, 256>>>(hidden, w_attn, b_attn, qkv_ptr,
                                        M, 3 * DD, DD);
    }

    // 2) ctx = causal_attention(q, k, v)     [8192, 1024] (heads merged)
    {
        dim3 grid(BB * HH, SS / 128);
        attention_kernel<<<grid, 128>>>(qkv_ptr, ctx_ptr);
    }

    // 3) out = ctx @ w_proj + b_proj         [8192, 1024]
    {
        dim3 grid(DD / 128, M / 128);
        gemm_tf32_kernel<<<grid, 256>>>(ctx_ptr, w_proj, b_proj, out,
                                        M, DD, DD);
    }
}

// round 3
// speedup vs baseline: 3.5382x; 2.3167x over previous
#include <cuda_runtime.h>
#include <cuda_bf16.h>
#include <math.h>

#define BB 4
#define SS 2048
#define DD 1024
#define HH 16
#define HDIM 64

__device__ float g_qkv[BB * SS * 3 * DD];   // [B,S,3D]
__device__ float g_ctx[BB * SS * DD];       // [B,S,D]

__device__ __forceinline__ unsigned f2tf32(float x) {
    unsigned r;
    asm("cvt.rna.tf32.f32 %0, %1;" : "=r"(r) : "f"(x));
    return r;
}

__device__ __forceinline__ void mma_tf32(float c[4],
                                         unsigned a0, unsigned a1,
                                         unsigned a2, unsigned a3,
                                         unsigned b0, unsigned b1) {
    asm volatile(
        "mma.sync.aligned.m16n8k8.row.col.f32.tf32.tf32.f32 "
        "{%0,%1,%2,%3}, {%4,%5,%6,%7}, {%8,%9}, {%0,%1,%2,%3};\n"
        : "+f"(c[0]), "+f"(c[1]), "+f"(c[2]), "+f"(c[3])
        : "r"(a0), "r"(a1), "r"(a2), "r"(a3), "r"(b0), "r"(b1));
}

// ---------------------------------------------------------------------------
// TF32 tensor-core GEMM (unchanged from R2): C = A @ W + bias
// ---------------------------------------------------------------------------
#define LDA_S 20
#define LDB_S 136

__global__ __launch_bounds__(256)
void gemm_tf32_kernel(const float* __restrict__ A,
                      const float* __restrict__ W,
                      const float* __restrict__ bias,
                      float* __restrict__ C,
                      int M, int N, int K)
{
    __shared__ float As[128 * LDA_S];
    __shared__ float Bs[16 * LDB_S];

    const int tid  = threadIdx.x;
    const int warp = tid >> 5;
    const int lane = tid & 31;
    const int gid  = lane >> 2;
    const int tig  = lane & 3;

    const int wm = warp >> 1;
    const int wn = warp & 1;

    const int row0 = blockIdx.y * 128;
    const int col0 = blockIdx.x * 128;

    float acc[2][8][4];
    #pragma unroll
    for (int i = 0; i < 2; i++)
        #pragma unroll
        for (int j = 0; j < 8; j++)
            #pragma unroll
            for (int v = 0; v < 4; v++) acc[i][j][v] = 0.f;

    const int ar = tid >> 1;
    const int ac = (tid & 1) * 8;
    const int br = tid >> 4;
    const int bc = (tid & 15) * 8;

    for (int k0 = 0; k0 < K; k0 += 16) {
        {
            const float* ap = A + (size_t)(row0 + ar) * K + k0 + ac;
            float4 v0 = *reinterpret_cast<const float4*>(ap);
            float4 v1 = *reinterpret_cast<const float4*>(ap + 4);
            float* dst = &As[ar * LDA_S + ac];
            dst[0] = __uint_as_float(f2tf32(v0.x));
            dst[1] = __uint_as_float(f2tf32(v0.y));
            dst[2] = __uint_as_float(f2tf32(v0.z));
            dst[3] = __uint_as_float(f2tf32(v0.w));
            dst[4] = __uint_as_float(f2tf32(v1.x));
            dst[5] = __uint_as_float(f2tf32(v1.y));
            dst[6] = __uint_as_float(f2tf32(v1.z));
            dst[7] = __uint_as_float(f2tf32(v1.w));
        }
        {
            const float* wp = W + (size_t)(k0 + br) * N + col0 + bc;
            float4 v0 = *reinterpret_cast<const float4*>(wp);
            float4 v1 = *reinterpret_cast<const float4*>(wp + 4);
            float* dst = &Bs[br * LDB_S + bc];
            dst[0] = __uint_as_float(f2tf32(v0.x));
            dst[1] = __uint_as_float(f2tf32(v0.y));
            dst[2] = __uint_as_float(f2tf32(v0.z));
            dst[3] = __uint_as_float(f2tf32(v0.w));
            dst[4] = __uint_as_float(f2tf32(v1.x));
            dst[5] = __uint_as_float(f2tf32(v1.y));
            dst[6] = __uint_as_float(f2tf32(v1.z));
            dst[7] = __uint_as_float(f2tf32(v1.w));
        }
        __syncthreads();

        #pragma unroll
        for (int kk = 0; kk < 16; kk += 8) {
            unsigned afrag[2][4];
            #pragma unroll
            for (int mi = 0; mi < 2; mi++) {
                int r = wm * 32 + mi * 16 + gid;
                afrag[mi][0] = __float_as_uint(As[r * LDA_S + kk + tig]);
                afrag[mi][1] = __float_as_uint(As[(r + 8) * LDA_S + kk + tig]);
                afrag[mi][2] = __float_as_uint(As[r * LDA_S + kk + tig + 4]);
                afrag[mi][3] = __float_as_uint(As[(r + 8) * LDA_S + kk + tig + 4]);
            }
            #pragma unroll
            for (int ni = 0; ni < 8; ni++) {
                int c = wn * 64 + ni * 8 + gid;
                unsigned b0 = __float_as_uint(Bs[(kk + tig) * LDB_S + c]);
                unsigned b1 = __float_as_uint(Bs[(kk + tig + 4) * LDB_S + c]);
                #pragma unroll
                for (int mi = 0; mi < 2; mi++)
                    mma_tf32(acc[mi][ni], afrag[mi][0], afrag[mi][1],
                             afrag[mi][2], afrag[mi][3], b0, b1);
            }
        }
        __syncthreads();
    }

    #pragma unroll
    for (int mi = 0; mi < 2; mi++) {
        int r = row0 + wm * 32 + mi * 16 + gid;
        #pragma unroll
        for (int ni = 0; ni < 8; ni++) {
            int c = col0 + wn * 64 + ni * 8 + 2 * tig;
            float bx = __ldg(&bias[c]);
            float by = __ldg(&bias[c + 1]);
            float2 o0 = make_float2(acc[mi][ni][0] + bx, acc[mi][ni][1] + by);
            float2 o1 = make_float2(acc[mi][ni][2] + bx, acc[mi][ni][3] + by);
            *reinterpret_cast<float2*>(&C[(size_t)r * N + c]) = o0;
            *reinterpret_cast<float2*>(&C[(size_t)(r + 8) * N + c]) = o1;
        }
    }
}

// ---------------------------------------------------------------------------
// Tensor-core causal flash attention (tf32 mma).
// grid = (B*H, S/64); 128 threads = 4 warps; warp = 16 query rows.
// Key tiles of 64. K/V in smem stride 72 (conflict-free b-frags).
// P accum->afrag conversion via shfl (no smem round trip).
// ---------------------------------------------------------------------------
#define KV_STRIDE 72

__global__ __launch_bounds__(128)
void attn_tc_kernel(const float* __restrict__ qkv, float* __restrict__ ctx)
{
    __shared__ float sm[2 * 64 * KV_STRIDE];   // 36864 B
    float* Qs = sm;                 // overlays Ks (Q consumed before K loads)
    float* Ks = sm;
    float* Vs = sm + 64 * KV_STRIDE;

    const int bh = blockIdx.x;
    const int b  = bh / HH;
    const int h  = bh % HH;
    const int qt = gridDim.y - 1 - blockIdx.y;   // long CTAs first
    const int q0 = qt * 64;

    const int tid  = threadIdx.x;
    const int warp = tid >> 5;
    const int lane = tid & 31;
    const int gid  = lane >> 2;
    const int tig  = lane & 3;
    const int wr0  = warp * 16;

    // ---- stage Q tile through smem (tf32), extract a-frags ----
    #pragma unroll
    for (int i = 0; i < 8; i++) {
        int idx = i * 128 + tid;
        int row = idx >> 4;
        int col = (idx & 15) * 4;
        float4 v = *reinterpret_cast<const float4*>(
            &qkv[((size_t)(b * SS + q0 + row)) * (3 * DD) + h * HDIM + col]);
        uint4 u;
        u.x = f2tf32(v.x); u.y = f2tf32(v.y);
        u.z = f2tf32(v.z); u.w = f2tf32(v.w);
        *reinterpret_cast<uint4*>(&Qs[row * KV_STRIDE + col]) = u;
    }
    __syncthreads();

    unsigned qa[8][4];
    #pragma unroll
    for (int kk = 0; kk < 8; kk++) {
        qa[kk][0] = __float_as_uint(Qs[(wr0 + gid)     * KV_STRIDE + kk * 8 + tig]);
        qa[kk][1] = __float_as_uint(Qs[(wr0 + gid + 8) * KV_STRIDE + kk * 8 + tig]);
        qa[kk][2] = __float_as_uint(Qs[(wr0 + gid)     * KV_STRIDE + kk * 8 + tig + 4]);
        qa[kk][3] = __float_as_uint(Qs[(wr0 + gid + 8) * KV_STRIDE + kk * 8 + tig + 4]);
    }
    __syncthreads();   // Qs free; Ks may overwrite

    float oacc[8][4];
    #pragma unroll
    for (int i = 0; i < 8; i++)
        #pragma unroll
        for (int j = 0; j < 4; j++) oacc[i][j] = 0.f;
    float m0 = -1e30f, m1 = -1e30f, l0 = 0.f, l1 = 0.f;

    for (int k0 = 0; k0 <= q0; k0 += 64) {
        // ---- load K/V tiles (64x64 each, tf32) ----
        #pragma unroll
        for (int i = 0; i < 8; i++) {
            int idx = i * 128 + tid;
            int row = idx >> 4;
            int col = (idx & 15) * 4;
            size_t base = ((size_t)(b * SS + k0 + row)) * (3 * DD)
                        + DD + h * HDIM + col;
            float4 kv = *reinterpret_cast<const float4*>(&qkv[base]);
            float4 vv = *reinterpret_cast<const float4*>(&qkv[base + DD]);
            uint4 ku, vu;
            ku.x = f2tf32(kv.x); ku.y = f2tf32(kv.y);
            ku.z = f2tf32(kv.z); ku.w = f2tf32(kv.w);
            vu.x = f2tf32(vv.x); vu.y = f2tf32(vv.y);
            vu.z = f2tf32(vv.z); vu.w = f2tf32(vv.w);
            *reinterpret_cast<uint4*>(&Ks[row * KV_STRIDE + col]) = ku;
            *reinterpret_cast<uint4*>(&Vs[row * KV_STRIDE + col]) = vu;
        }
        __syncthreads();

        // ---- S = Q K^T ----
        float sacc[8][4];
        #pragma unroll
        for (int ni = 0; ni < 8; ni++) {
            sacc[ni][0] = sacc[ni][1] = sacc[ni][2] = sacc[ni][3] = 0.f;
            #pragma unroll
            for (int kk = 0; kk < 8; kk++) {
                unsigned b0 = __float_as_uint(
                    Ks[(ni * 8 + gid) * KV_STRIDE + kk * 8 + tig]);
                unsigned b1 = __float_as_uint(
                    Ks[(ni * 8 + gid) * KV_STRIDE + kk * 8 + tig + 4]);
                mma_tf32(sacc[ni], qa[kk][0], qa[kk][1], qa[kk][2], qa[kk][3],
                         b0, b1);
            }
        }

        // ---- scale + causal mask (diagonal tile only) ----
        const bool diag = (k0 == q0);
        const int row_l0 = wr0 + gid;
        #pragma unroll
        for (int ni = 0; ni < 8; ni++) {
            #pragma unroll
            for (int v = 0; v < 4; v++) sacc[ni][v] *= 0.125f;
            if (diag) {
                int c = ni * 8 + 2 * tig;
                if (c     > row_l0)     sacc[ni][0] = -1e30f;
                if (c + 1 > row_l0)     sacc[ni][1] = -1e30f;
                if (c     > row_l0 + 8) sacc[ni][2] = -1e30f;
                if (c + 1 > row_l0 + 8) sacc[ni][3] = -1e30f;
            }
        }

        // ---- online softmax ----
        float tmax0 = -1e30f, tmax1 = -1e30f;
        #pragma unroll
        for (int ni = 0; ni < 8; ni++) {
            tmax0 = fmaxf(tmax0, fmaxf(sacc[ni][0], sacc[ni][1]));
            tmax1 = fmaxf(tmax1, fmaxf(sacc[ni][2], sacc[ni][3]));
        }
        tmax0 = fmaxf(tmax0, __shfl_xor_sync(0xffffffffu, tmax0, 1));
        tmax0 = fmaxf(tmax0, __shfl_xor_sync(0xffffffffu, tmax0, 2));
        tmax1 = fmaxf(tmax1, __shfl_xor_sync(0xffffffffu, tmax1, 1));
        tmax1 = fmaxf(tmax1, __shfl_xor_sync(0xffffffffu, tmax1, 2));

        float mn0 = fmaxf(m0, tmax0);
        float mn1 = fmaxf(m1, tmax1);
        float c0 = __expf(m0 - mn0);
        float c1 = __expf(m1 - mn1);
        m0 = mn0; m1 = mn1;

        float s0 = 0.f, s1 = 0.f;
        #pragma unroll
        for (int ni = 0; ni < 8; ni++) {
            float p0 = __expf(sacc[ni][0] - mn0);
            float p1 = __expf(sacc[ni][1] - mn0);
            float p2 = __expf(sacc[ni][2] - mn1);
            float p3 = __expf(sacc[ni][3] - mn1);
            s0 += p0 + p1;
            s1 += p2 + p3;
            // store tf32 bits back into sacc for the PV phase
            sacc[ni][0] = __uint_as_float(f2tf32(p0));
            sacc[ni][1] = __uint_as_float(f2tf32(p1));
            sacc[ni][2] = __uint_as_float(f2tf32(p2));
            sacc[ni][3] = __uint_as_float(f2tf32(p3));
            oacc[ni][0] *= c0; oacc[ni][1] *= c0;
            oacc[ni][2] *= c1; oacc[ni][3] *= c1;
        }
        s0 += __shfl_xor_sync(0xffffffffu, s0, 1);
        s0 += __shfl_xor_sync(0xffffffffu, s0, 2);
        s1 += __shfl_xor_sync(0xffffffffu, s1, 1);
        s1 += __shfl_xor_sync(0xffffffffu, s1, 2);
        l0 = l0 * c0 + s0;
        l1 = l1 * c1 + s1;

        // ---- O += P V ----
        const int base_lane = lane & ~3;
        #pragma unroll
        for (int kk = 0; kk < 8; kk++) {
            int src1 = base_lane + (tig >> 1);
            int src2 = src1 + 2;
            float v0 = __shfl_sync(0xffffffffu, sacc[kk][0], src1);
            float v1 = __shfl_sync(0xffffffffu, sacc[kk][1], src1);
            float v2 = __shfl_sync(0xffffffffu, sacc[kk][2], src1);
            float v3 = __shfl_sync(0xffffffffu, sacc[kk][3], src1);
            float w0 = __shfl_sync(0xffffffffu, sacc[kk][0], src2);
            float w1 = __shfl_sync(0xffffffffu, sacc[kk][1], src2);
            float w2 = __shfl_sync(0xffffffffu, sacc[kk][2], src2);
            float w3 = __shfl_sync(0xffffffffu, sacc[kk][3], src2);
            bool odd = (tig & 1);
            unsigned pa0 = __float_as_uint(odd ? v1 : v0);
            unsigned pa1 = __float_as_uint(odd ? v3 : v2);
            unsigned pa2 = __float_as_uint(odd ? w1 : w0);
            unsigned pa3 = __float_as_uint(odd ? w3 : w2);
            #pragma unroll
            for (int ni = 0; ni < 8; ni++) {
                unsigned b0 = __float_as_uint(
                    Vs[(kk * 8 + tig)     * KV_STRIDE + ni * 8 + gid]);
                unsigned b1 = __float_as_uint(
                    Vs[(kk * 8 + tig + 4) * KV_STRIDE + ni * 8 + gid]);
                mma_tf32(oacc[ni], pa0, pa1, pa2, pa3, b0, b1);
            }
        }
        __syncthreads();   // before next tile overwrites Ks/Vs
    }

    // ---- normalize + write ----
    float inv0 = 1.f / l0;
    float inv1 = 1.f / l1;
    int row0 = q0 + wr0 + gid;
    int row1 = row0 + 8;
    #pragma unroll
    for (int ni = 0; ni < 8; ni++) {
        int d = h * HDIM + ni * 8 + 2 * tig;
        float2 o0 = make_float2(oacc[ni][0] * inv0, oacc[ni][1] * inv0);
        float2 o1 = make_float2(oacc[ni][2] * inv1, oacc[ni][3] * inv1);
        *reinterpret_cast<float2*>(&ctx[((size_t)(b * SS + row0)) * DD + d]) = o0;
        *reinterpret_cast<float2*>(&ctx[((size_t)(b * SS + row1)) * DD + d]) = o1;
    }
}

// ---------------------------------------------------------------------------
// Launch
// ---------------------------------------------------------------------------
extern "C" void kernel_launch(void* const* d_in, const int* in_sizes, int n_in,
                              void* d_out, int out_size)
{
    const float* hidden = (const float*)d_in[0];
    const float* w_attn = (const float*)d_in[1];
    const float* b_attn = (const float*)d_in[2];
    const float* w_proj = (const float*)d_in[3];
    const float* b_proj = (const float*)d_in[4];
    float* out = (float*)d_out;

    float *qkv_ptr = nullptr, *ctx_ptr = nullptr;
    cudaGetSymbolAddress((void**)&qkv_ptr, g_qkv);
    cudaGetSymbolAddress((void**)&ctx_ptr, g_ctx);

    const int M = BB * SS;

    {
        dim3 grid(3 * DD / 128, M / 128);
        gemm_tf32_kernel<<<grid, 256>>>(hidden, w_attn, b_attn, qkv_ptr,
                                        M, 3 * DD, DD);
    }
    {
        dim3 grid(BB * HH, SS / 64);
        attn_tc_kernel<<<grid, 128>>>(qkv_ptr, ctx_ptr);
    }
    {
        dim3 grid(DD / 128, M / 128);
        gemm_tf32_kernel<<<grid, 256>>>(ctx_ptr, w_proj, b_proj, out,
                                        M, DD, DD);
    }
}

// round 4
// speedup vs baseline: 3.6026x; 1.0182x over previous
#include <cuda_runtime.h>
#include <cuda_bf16.h>
#include <math.h>

#define BB 4
#define SS 2048
#define DD 1024
#define HH 16
#define HDIM 64

__device__ float g_qkv[BB * SS * 3 * DD];   // [B,S,3D]
__device__ float g_ctx[BB * SS * DD];       // [B,S,D]

__device__ __forceinline__ unsigned f2tf32(float x) {
    unsigned r;
    asm("cvt.rna.tf32.f32 %0, %1;" : "=r"(r) : "f"(x));
    return r;
}

__device__ __forceinline__ void mma_tf32(float c[4],
                                         unsigned a0, unsigned a1,
                                         unsigned a2, unsigned a3,
                                         unsigned b0, unsigned b1) {
    asm volatile(
        "mma.sync.aligned.m16n8k8.row.col.f32.tf32.tf32.f32 "
        "{%0,%1,%2,%3}, {%4,%5,%6,%7}, {%8,%9}, {%0,%1,%2,%3};\n"
        : "+f"(c[0]), "+f"(c[1]), "+f"(c[2]), "+f"(c[3])
        : "r"(a0), "r"(a1), "r"(a2), "r"(a3), "r"(b0), "r"(b1));
}

// ---------------------------------------------------------------------------
// TF32 GEMM v2: C[M,N] = A[M,K] @ W[K,N] + bias
// CTA 128x256, BK=16, 8 warps (2x4), warp tile 64x64, double-buffered smem.
// As stride 20; Bs stride 296 with col' = c + (c>>5)*4 pad-swizzle
// (b-frag LDS and STS.128 staging both bank-conflict-free).
// ---------------------------------------------------------------------------
#define G_LDA 20
#define G_LDB 296
#define A_WORDS (128 * G_LDA)
#define B_WORDS (16 * G_LDB)
#define GSMEM_BYTES ((A_WORDS + B_WORDS) * 2 * 4)

__device__ __forceinline__ int bcolmap(int c) { return c + ((c >> 5) << 2); }

__global__ __launch_bounds__(256, 1)
void gemm_tf32_v2(const float* __restrict__ A,
                  const float* __restrict__ W,
                  const float* __restrict__ bias,
                  float* __restrict__ C,
                  int M, int N, int K)
{
    extern __shared__ float sm[];
    float* As[2] = { sm, sm + A_WORDS };
    float* Bs[2] = { sm + 2 * A_WORDS, sm + 2 * A_WORDS + B_WORDS };

    const int tid  = threadIdx.x;
    const int warp = tid >> 5;
    const int lane = tid & 31;
    const int gid  = lane >> 2;
    const int tig  = lane & 3;

    const int wm = warp >> 2;          // 0..1 -> 64-row block
    const int wn = warp & 3;           // 0..3 -> 64-col block

    const int row0 = blockIdx.y * 128;
    const int col0 = blockIdx.x * 256;

    float acc[4][8][4];
    #pragma unroll
    for (int i = 0; i < 4; i++)
        #pragma unroll
        for (int j = 0; j < 8; j++)
            #pragma unroll
            for (int v = 0; v < 4; v++) acc[i][j][v] = 0.f;

    // staging indices
    const int ar = tid >> 1;               // 0..127
    const int ac = (tid & 1) * 8;          // 0 / 8
    const int br = tid >> 4;               // 0..15
    const int bn0 = (tid & 15) * 16;       // 0..240
    const int bcol = bn0 + ((bn0 >> 5) << 2);   // padded col base

    const float* Aip = A + (size_t)(row0 + ar) * K + ac;
    const float* Wip = W + (size_t)br * N + col0 + bn0;

    float4 a0r, a1r, b0r, b1r, b2r, b3r;

    #define LDG_ITER(K0)                                                     \
        do {                                                                 \
            const float* ap = Aip + (K0);                                    \
            a0r = *reinterpret_cast<const float4*>(ap);                      \
            a1r = *reinterpret_cast<const float4*>(ap + 4);                  \
            const float* wp = Wip + (size_t)(K0) * N;                        \
            b0r = *reinterpret_cast<const float4*>(wp);                      \
            b1r = *reinterpret_cast<const float4*>(wp + 4);                  \
            b2r = *reinterpret_cast<const float4*>(wp + 8);                  \
            b3r = *reinterpret_cast<const float4*>(wp + 12);                 \
        } while (0)

    #define STS_ITER(BUF)                                                    \
        do {                                                                 \
            float* ad = &As[BUF][ar * G_LDA + ac];                           \
            uint4 u0, u1;                                                    \
            u0.x = f2tf32(a0r.x); u0.y = f2tf32(a0r.y);                      \
            u0.z = f2tf32(a0r.z); u0.w = f2tf32(a0r.w);                      \
            u1.x = f2tf32(a1r.x); u1.y = f2tf32(a1r.y);                      \
            u1.z = f2tf32(a1r.z); u1.w = f2tf32(a1r.w);                      \
            *reinterpret_cast<uint4*>(ad)     = u0;                          \
            *reinterpret_cast<uint4*>(ad + 4) = u1;                          \
            float* bd = &Bs[BUF][br * G_LDB + bcol];                         \
            uint4 v0, v1, v2, v3;                                            \
            v0.x = f2tf32(b0r.x); v0.y = f2tf32(b0r.y);                      \
            v0.z = f2tf32(b0r.z); v0.w = f2tf32(b0r.w);                      \
            v1.x = f2tf32(b1r.x); v1.y = f2tf32(b1r.y);                      \
            v1.z = f2tf32(b1r.z); v1.w = f2tf32(b1r.w);                      \
            v2.x = f2tf32(b2r.x); v2.y = f2tf32(b2r.y);                      \
            v2.z = f2tf32(b2r.z); v2.w = f2tf32(b2r.w);                      \
            v3.x = f2tf32(b3r.x); v3.y = f2tf32(b3r.y);                      \
            v3.z = f2tf32(b3r.z); v3.w = f2tf32(b3r.w);                      \
            *reinterpret_cast<uint4*>(bd)      = v0;                         \
            *reinterpret_cast<uint4*>(bd + 4)  = v1;                         \
            *reinterpret_cast<uint4*>(bd + 8)  = v2;                         \
            *reinterpret_cast<uint4*>(bd + 12) = v3;                         \
        } while (0)

    LDG_ITER(0);
    STS_ITER(0);
    __syncthreads();

    int buf = 0;
    for (int k0 = 0; k0 < K; k0 += 16) {
        const bool has_next = (k0 + 16 < K);
        if (has_next) LDG_ITER(k0 + 16);

        const float* Ac = As[buf];
        const float* Bc = Bs[buf];
        #pragma unroll
        for (int kk = 0; kk < 16; kk += 8) {
            unsigned afrag[4][4];
            #pragma unroll
            for (int mi = 0; mi < 4; mi++) {
                int r = wm * 64 + mi * 16 + gid;
                afrag[mi][0] = __float_as_uint(Ac[r * G_LDA + kk + tig]);
                afrag[mi][1] = __float_as_uint(Ac[(r + 8) * G_LDA + kk + tig]);
                afrag[mi][2] = __float_as_uint(Ac[r * G_LDA + kk + tig + 4]);
                afrag[mi][3] = __float_as_uint(Ac[(r + 8) * G_LDA + kk + tig + 4]);
            }
            #pragma unroll
            for (int ni = 0; ni < 8; ni++) {
                int c = bcolmap(wn * 64 + ni * 8 + gid);
                unsigned b0 = __float_as_uint(Bc[(kk + tig) * G_LDB + c]);
                unsigned b1 = __float_as_uint(Bc[(kk + tig + 4) * G_LDB + c]);
                #pragma unroll
                for (int mi = 0; mi < 4; mi++)
                    mma_tf32(acc[mi][ni], afrag[mi][0], afrag[mi][1],
                             afrag[mi][2], afrag[mi][3], b0, b1);
            }
        }

        if (has_next) STS_ITER(buf ^ 1);
        __syncthreads();
        buf ^= 1;
    }

    // epilogue
    #pragma unroll
    for (int mi = 0; mi < 4; mi++) {
        int r = row0 + wm * 64 + mi * 16 + gid;
        #pragma unroll
        for (int ni = 0; ni < 8; ni++) {
            int c = col0 + wn * 64 + ni * 8 + 2 * tig;
            float bx = __ldg(&bias[c]);
            float by = __ldg(&bias[c + 1]);
            float2 o0 = make_float2(acc[mi][ni][0] + bx, acc[mi][ni][1] + by);
            float2 o1 = make_float2(acc[mi][ni][2] + bx, acc[mi][ni][3] + by);
            *reinterpret_cast<float2*>(&C[(size_t)r * N + c]) = o0;
            *reinterpret_cast<float2*>(&C[(size_t)(r + 8) * N + c]) = o1;
        }
    }
}

// ---------------------------------------------------------------------------
// Tensor-core causal flash attention (unchanged from R3).
// ---------------------------------------------------------------------------
#define KV_STRIDE 72

__global__ __launch_bounds__(128)
void attn_tc_kernel(const float* __restrict__ qkv, float* __restrict__ ctx)
{
    __shared__ float sm[2 * 64 * KV_STRIDE];
    float* Qs = sm;
    float* Ks = sm;
    float* Vs = sm + 64 * KV_STRIDE;

    const int bh = blockIdx.x;
    const int b  = bh / HH;
    const int h  = bh % HH;
    const int qt = gridDim.y - 1 - blockIdx.y;
    const int q0 = qt * 64;

    const int tid  = threadIdx.x;
    const int warp = tid >> 5;
    const int lane = tid & 31;
    const int gid  = lane >> 2;
    const int tig  = lane & 3;
    const int wr0  = warp * 16;

    #pragma unroll
    for (int i = 0; i < 8; i++) {
        int idx = i * 128 + tid;
        int row = idx >> 4;
        int col = (idx & 15) * 4;
        float4 v = *reinterpret_cast<const float4*>(
            &qkv[((size_t)(b * SS + q0 + row)) * (3 * DD) + h * HDIM + col]);
        uint4 u;
        u.x = f2tf32(v.x); u.y = f2tf32(v.y);
        u.z = f2tf32(v.z); u.w = f2tf32(v.w);
        *reinterpret_cast<uint4*>(&Qs[row * KV_STRIDE + col]) = u;
    }
    __syncthreads();

    unsigned qa[8][4];
    #pragma unroll
    for (int kk = 0; kk < 8; kk++) {
        qa[kk][0] = __float_as_uint(Qs[(wr0 + gid)     * KV_STRIDE + kk * 8 + tig]);
        qa[kk][1] = __float_as_uint(Qs[(wr0 + gid + 8) * KV_STRIDE + kk * 8 + tig]);
        qa[kk][2] = __float_as_uint(Qs[(wr0 + gid)     * KV_STRIDE + kk * 8 + tig + 4]);
        qa[kk][3] = __float_as_uint(Qs[(wr0 + gid + 8) * KV_STRIDE + kk * 8 + tig + 4]);
    }
    __syncthreads();

    float oacc[8][4];
    #pragma unroll
    for (int i = 0; i < 8; i++)
        #pragma unroll
        for (int j = 0; j < 4; j++) oacc[i][j] = 0.f;
    float m0 = -1e30f, m1 = -1e30f, l0 = 0.f, l1 = 0.f;

    for (int k0 = 0; k0 <= q0; k0 += 64) {
        #pragma unroll
        for (int i = 0; i < 8; i++) {
            int idx = i * 128 + tid;
            int row = idx >> 4;
            int col = (idx & 15) * 4;
            size_t base = ((size_t)(b * SS + k0 + row)) * (3 * DD)
                        + DD + h * HDIM + col;
            float4 kv = *reinterpret_cast<const float4*>(&qkv[base]);
            float4 vv = *reinterpret_cast<const float4*>(&qkv[base + DD]);
            uint4 ku, vu;
            ku.x = f2tf32(kv.x); ku.y = f2tf32(kv.y);
            ku.z = f2tf32(kv.z); ku.w = f2tf32(kv.w);
            vu.x = f2tf32(vv.x); vu.y = f2tf32(vv.y);
            vu.z = f2tf32(vv.z); vu.w = f2tf32(vv.w);
            *reinterpret_cast<uint4*>(&Ks[row * KV_STRIDE + col]) = ku;
            *reinterpret_cast<uint4*>(&Vs[row * KV_STRIDE + col]) = vu;
        }
        __syncthreads();

        float sacc[8][4];
        #pragma unroll
        for (int ni = 0; ni < 8; ni++) {
            sacc[ni][0] = sacc[ni][1] = sacc[ni][2] = sacc[ni][3] = 0.f;
            #pragma unroll
            for (int kk = 0; kk < 8; kk++) {
                unsigned b0 = __float_as_uint(
                    Ks[(ni * 8 + gid) * KV_STRIDE + kk * 8 + tig]);
                unsigned b1 = __float_as_uint(
                    Ks[(ni * 8 + gid) * KV_STRIDE + kk * 8 + tig + 4]);
                mma_tf32(sacc[ni], qa[kk][0], qa[kk][1], qa[kk][2], qa[kk][3],
                         b0, b1);
            }
        }

        const bool diag = (k0 == q0);
        const int row_l0 = wr0 + gid;
        #pragma unroll
        for (int ni = 0; ni < 8; ni++) {
            #pragma unroll
            for (int v = 0; v < 4; v++) sacc[ni][v] *= 0.125f;
            if (diag) {
                int c = ni * 8 + 2 * tig;
                if (c     > row_l0)     sacc[ni][0] = -1e30f;
                if (c + 1 > row_l0)     sacc[ni][1] = -1e30f;
                if (c     > row_l0 + 8) sacc[ni][2] = -1e30f;
                if (c + 1 > row_l0 + 8) sacc[ni][3] = -1e30f;
            }
        }

        float tmax0 = -1e30f, tmax1 = -1e30f;
        #pragma unroll
        for (int ni = 0; ni < 8; ni++) {
            tmax0 = fmaxf(tmax0, fmaxf(sacc[ni][0], sacc[ni][1]));
            tmax1 = fmaxf(tmax1, fmaxf(sacc[ni][2], sacc[ni][3]));
        }
        tmax0 = fmaxf(tmax0, __shfl_xor_sync(0xffffffffu, tmax0, 1));
        tmax0 = fmaxf(tmax0, __shfl_xor_sync(0xffffffffu, tmax0, 2));
        tmax1 = fmaxf(tmax1, __shfl_xor_sync(0xffffffffu, tmax1, 1));
        tmax1 = fmaxf(tmax1, __shfl_xor_sync(0xffffffffu, tmax1, 2));

        float mn0 = fmaxf(m0, tmax0);
        float mn1 = fmaxf(m1, tmax1);
        float c0 = __expf(m0 - mn0);
        float c1 = __expf(m1 - mn1);
        m0 = mn0; m1 = mn1;

        float s0 = 0.f, s1 = 0.f;
        #pragma unroll
        for (int ni = 0; ni < 8; ni++) {
            float p0 = __expf(sacc[ni][0] - mn0);
            float p1 = __expf(sacc[ni][1] - mn0);
            float p2 = __expf(sacc[ni][2] - mn1);
            float p3 = __expf(sacc[ni][3] - mn1);
            s0 += p0 + p1;
            s1 += p2 + p3;
            sacc[ni][0] = __uint_as_float(f2tf32(p0));
            sacc[ni][1] = __uint_as_float(f2tf32(p1));
            sacc[ni][2] = __uint_as_float(f2tf32(p2));
            sacc[ni][3] = __uint_as_float(f2tf32(p3));
            oacc[ni][0] *= c0; oacc[ni][1] *= c0;
            oacc[ni][2] *= c1; oacc[ni][3] *= c1;
        }
        s0 += __shfl_xor_sync(0xffffffffu, s0, 1);
        s0 += __shfl_xor_sync(0xffffffffu, s0, 2);
        s1 += __shfl_xor_sync(0xffffffffu, s1, 1);
        s1 += __shfl_xor_sync(0xffffffffu, s1, 2);
        l0 = l0 * c0 + s0;
        l1 = l1 * c1 + s1;

        const int base_lane = lane & ~3;
        #pragma unroll
        for (int kk = 0; kk < 8; kk++) {
            int src1 = base_lane + (tig >> 1);
            int src2 = src1 + 2;
            float v0 = __shfl_sync(0xffffffffu, sacc[kk][0], src1);
            float v1 = __shfl_sync(0xffffffffu, sacc[kk][1], src1);
            float v2 = __shfl_sync(0xffffffffu, sacc[kk][2], src1);
            float v3 = __shfl_sync(0xffffffffu, sacc[kk][3], src1);
            float w0 = __shfl_sync(0xffffffffu, sacc[kk][0], src2);
            float w1 = __shfl_sync(0xffffffffu, sacc[kk][1], src2);
            float w2 = __shfl_sync(0xffffffffu, sacc[kk][2], src2);
            float w3 = __shfl_sync(0xffffffffu, sacc[kk][3], src2);
            bool odd = (tig & 1);
            unsigned pa0 = __float_as_uint(odd ? v1 : v0);
            unsigned pa1 = __float_as_uint(odd ? v3 : v2);
            unsigned pa2 = __float_as_uint(odd ? w1 : w0);
            unsigned pa3 = __float_as_uint(odd ? w3 : w2);
            #pragma unroll
            for (int ni = 0; ni < 8; ni++) {
                unsigned b0 = __float_as_uint(
                    Vs[(kk * 8 + tig)     * KV_STRIDE + ni * 8 + gid]);
                unsigned b1 = __float_as_uint(
                    Vs[(kk * 8 + tig + 4) * KV_STRIDE + ni * 8 + gid]);
                mma_tf32(oacc[ni], pa0, pa1, pa2, pa3, b0, b1);
            }
        }
        __syncthreads();
    }

    float inv0 = 1.f / l0;
    float inv1 = 1.f / l1;
    int row0 = q0 + wr0 + gid;
    int row1 = row0 + 8;
    #pragma unroll
    for (int ni = 0; ni < 8; ni++) {
        int d = h * HDIM + ni * 8 + 2 * tig;
        float2 o0 = make_float2(oacc[ni][0] * inv0, oacc[ni][1] * inv0);
        float2 o1 = make_float2(oacc[ni][2] * inv1, oacc[ni][3] * inv1);
        *reinterpret_cast<float2*>(&ctx[((size_t)(b * SS + row0)) * DD + d]) = o0;
        *reinterpret_cast<float2*>(&ctx[((size_t)(b * SS + row1)) * DD + d]) = o1;
    }
}

// ---------------------------------------------------------------------------
// Launch
// ---------------------------------------------------------------------------
extern "C" void kernel_launch(void* const* d_in, const int* in_sizes, int n_in,
                              void* d_out, int out_size)
{
    const float* hidden = (const float*)d_in[0];
    const float* w_attn = (const float*)d_in[1];
    const float* b_attn = (const float*)d_in[2];
    const float* w_proj = (const float*)d_in[3];
    const float* b_proj = (const float*)d_in[4];
    float* out = (float*)d_out;

    float *qkv_ptr = nullptr, *ctx_ptr = nullptr;
    cudaGetSymbolAddress((void**)&qkv_ptr, g_qkv);
    cudaGetSymbolAddress((void**)&ctx_ptr, g_ctx);

    static bool attr_done = false;
    if (!attr_done) {
        cudaFuncSetAttribute(gemm_tf32_v2,
                             cudaFuncAttributeMaxDynamicSharedMemorySize,
                             GSMEM_BYTES);
        attr_done = true;
    }

    const int M = BB * SS;

    {
        dim3 grid(3 * DD / 256, M / 128);
        gemm_tf32_v2<<<grid, 256, GSMEM_BYTES>>>(hidden, w_attn, b_attn,
                                                 qkv_ptr, M, 3 * DD, DD);
    }
    {
        dim3 grid(BB * HH, SS / 64);
        attn_tc_kernel<<<grid, 128>>>(qkv_ptr, ctx_ptr);
    }
    {
        dim3 grid(DD / 256, M / 128);
        gemm_tf32_v2<<<grid, 256, GSMEM_BYTES>>>(ctx_ptr, w_proj, b_proj,
                                                 out, M, DD, DD);
    }
}

// round 6
// speedup vs baseline: 8.9219x; 2.4765x over previous
#include <cuda_runtime.h>
#include <cuda_fp16.h>
#include <math.h>
#include <stdint.h>

#define BB 4
#define SS 2048
#define DD 1024
#define HH 16
#define HDIM 64

// fp16 scratch (device globals: allocation-free per harness rules)
__device__ __half g_h16[BB * SS * DD];          // hidden fp16
__device__ __half g_wa16[DD * 3 * DD];          // w_attn fp16
__device__ __half g_wp16[DD * DD];              // w_proj fp16
__device__ __half g_qkv16[BB * SS * 3 * DD];    // qkv fp16
__device__ __half g_ctx16[BB * SS * DD];        // ctx fp16

// ---------------------------------------------------------------------------
// helpers
// ---------------------------------------------------------------------------
__device__ __forceinline__ uint32_t smem_u32(const void* p) {
    uint32_t a;
    asm("{ .reg .u64 t; cvta.to.shared.u64 t, %1; cvt.u32.u64 %0, t; }"
        : "=r"(a) : "l"(p));
    return a;
}

__device__ __forceinline__ void cpa16(uint32_t dst, const void* src) {
    asm volatile("cp.async.ca.shared.global [%0], [%1], 16;"
                 :: "r"(dst), "l"(src));
}
#define CP_COMMIT() asm volatile("cp.async.commit_group;")
#define CP_WAIT(n)  asm volatile("cp.async.wait_group %0;" :: "n"(n))

__device__ __forceinline__ void ldsm_x4(uint32_t* d, uint32_t addr) {
    asm volatile("ldmatrix.sync.aligned.m8n8.x4.shared.b16 {%0,%1,%2,%3}, [%4];"
                 : "=r"(d[0]), "=r"(d[1]), "=r"(d[2]), "=r"(d[3]) : "r"(addr));
}
__device__ __forceinline__ void ldsm_x4t(uint32_t* d, uint32_t addr) {
    asm volatile("ldmatrix.sync.aligned.m8n8.x4.trans.shared.b16 {%0,%1,%2,%3}, [%4];"
                 : "=r"(d[0]), "=r"(d[1]), "=r"(d[2]), "=r"(d[3]) : "r"(addr));
}

__device__ __forceinline__ void mma_f16(float* c, const uint32_t* a,
                                        uint32_t b0, uint32_t b1) {
    asm volatile(
        "mma.sync.aligned.m16n8k16.row.col.f32.f16.f16.f32 "
        "{%0,%1,%2,%3}, {%4,%5,%6,%7}, {%8,%9}, {%0,%1,%2,%3};"
        : "+f"(c[0]), "+f"(c[1]), "+f"(c[2]), "+f"(c[3])
        : "r"(a[0]), "r"(a[1]), "r"(a[2]), "r"(a[3]), "r"(b0), "r"(b1));
}

__device__ __forceinline__ uint32_t h2bits(float x, float y) {
    __half2 h = __floats2half2_rn(x, y);
    return *reinterpret_cast<uint32_t*>(&h);
}

// ---------------------------------------------------------------------------
// fp32 -> fp16 conversion
// ---------------------------------------------------------------------------
__global__ void f32_to_f16_kernel(const float4* __restrict__ src,
                                  uint2* __restrict__ dst, int n4)
{
    int i = blockIdx.x * blockDim.x + threadIdx.x;
    if (i < n4) {
        float4 v = src[i];
        uint2 u;
        u.x = h2bits(v.x, v.y);
        u.y = h2bits(v.z, v.w);
        dst[i] = u;
    }
}

// ---------------------------------------------------------------------------
// fp16 tensor-core GEMM: C[M,N] = A[M,K] @ W[K,N] + bias
// CTA 128x128, BK=32, 8 warps (4x2), warp 32x64, cp.async double-buffered.
// A smem [row][k] stride 40 halves; B smem [k][n] stride 136 halves.
// ---------------------------------------------------------------------------
#define LDAH 40
#define LDBH 136

template<int OUT16>
__global__ __launch_bounds__(256, 2)
void gemm_f16(const __half* __restrict__ A, const __half* __restrict__ W,
              const float* __restrict__ bias, void* __restrict__ Cout,
              int M, int N, int K)
{
    __shared__ __half As[2][128 * LDAH];
    __shared__ __half Bs[2][32 * LDBH];

    const int tid  = threadIdx.x;
    const int warp = tid >> 5;
    const int lane = tid & 31;
    const int gid  = lane >> 2;
    const int tig  = lane & 3;
    const int wm = warp >> 1;          // 0..3
    const int wn = warp & 1;           // 0..1

    const int row0 = blockIdx.y * 128;
    const int col0 = blockIdx.x * 128;

    float acc[2][8][4];
    #pragma unroll
    for (int i = 0; i < 2; i++)
        #pragma unroll
        for (int j = 0; j < 8; j++)
            #pragma unroll
            for (int v = 0; v < 4; v++) acc[i][j][v] = 0.f;

    #define GSTAGE(BUF, KT)                                                   \
        do {                                                                  \
            _Pragma("unroll")                                                 \
            for (int j = 0; j < 2; j++) {                                     \
                int idx = j * 256 + tid;                                      \
                int r = idx >> 2, c = idx & 3;                                \
                cpa16(smem_u32(&As[BUF][r * LDAH + c * 8]),                   \
                      A + (size_t)(row0 + r) * K + (KT) * 32 + c * 8);        \
            }                                                                 \
            _Pragma("unroll")                                                 \
            for (int j = 0; j < 2; j++) {                                     \
                int idx = j * 256 + tid;                                      \
                int kr = idx >> 4, c = idx & 15;                              \
                cpa16(smem_u32(&Bs[BUF][kr * LDBH + c * 8]),                  \
                      W + (size_t)((KT) * 32 + kr) * N + col0 + c * 8);       \
            }                                                                 \
        } while (0)

    // lane bases for ldmatrix
    const int i = lane;
    const int a_lrow = wm * 32 + (i & 7) + ((i >> 3) & 1) * 8;
    const int a_lk   = ((i >> 4) & 1) * 8;
    const int b_lk   = (i & 7) + ((i >> 3) & 1) * 8;
    const int b_lc   = wn * 64 + ((i >> 4) & 1) * 8;

    GSTAGE(0, 0);
    CP_COMMIT();

    const int NT = K / 32;
    int buf = 0;
    for (int t = 0; t < NT; t++) {
        if (t + 1 < NT) {
            GSTAGE(buf ^ 1, t + 1);
            CP_COMMIT();
            CP_WAIT(1);
        } else {
            CP_WAIT(0);
        }
        __syncthreads();

        const uint32_t abase = smem_u32(&As[buf][a_lrow * LDAH + a_lk]);
        const uint32_t bbase = smem_u32(&Bs[buf][b_lk * LDBH + b_lc]);
        #pragma unroll
        for (int ks = 0; ks < 2; ks++) {
            uint32_t af[2][4];
            ldsm_x4(af[0], abase + ks * 32);
            ldsm_x4(af[1], abase + 16 * LDAH * 2 + ks * 32);
            uint32_t bf[4][4];
            #pragma unroll
            for (int nb = 0; nb < 4; nb++)
                ldsm_x4t(bf[nb], bbase + (ks * 16 * LDBH + nb * 16) * 2);
            #pragma unroll
            for (int nb = 0; nb < 4; nb++)
                #pragma unroll
                for (int hn = 0; hn < 2; hn++) {
                    int ni = nb * 2 + hn;
                    mma_f16(acc[0][ni], af[0], bf[nb][hn * 2], bf[nb][hn * 2 + 1]);
                    mma_f16(acc[1][ni], af[1], bf[nb][hn * 2], bf[nb][hn * 2 + 1]);
                }
        }
        __syncthreads();
        buf ^= 1;
    }

    // epilogue
    #pragma unroll
    for (int mi = 0; mi < 2; mi++) {
        int r = row0 + wm * 32 + mi * 16 + gid;
        #pragma unroll
        for (int ni = 0; ni < 8; ni++) {
            int c = col0 + wn * 64 + ni * 8 + 2 * tig;
            float bx = __ldg(&bias[c]);
            float by = __ldg(&bias[c + 1]);
            if (OUT16) {
                __half* C16 = (__half*)Cout;
                __half2 h0 = __floats2half2_rn(acc[mi][ni][0] + bx,
                                               acc[mi][ni][1] + by);
                __half2 h1 = __floats2half2_rn(acc[mi][ni][2] + bx,
                                               acc[mi][ni][3] + by);
                *reinterpret_cast<__half2*>(&C16[(size_t)r * N + c]) = h0;
                *reinterpret_cast<__half2*>(&C16[(size_t)(r + 8) * N + c]) = h1;
            } else {
                float* C32 = (float*)Cout;
                float2 o0 = make_float2(acc[mi][ni][0] + bx, acc[mi][ni][1] + by);
                float2 o1 = make_float2(acc[mi][ni][2] + bx, acc[mi][ni][3] + by);
                *reinterpret_cast<float2*>(&C32[(size_t)r * N + c]) = o0;
                *reinterpret_cast<float2*>(&C32[(size_t)(r + 8) * N + c]) = o1;
            }
        }
    }
}

// ---------------------------------------------------------------------------
// fp16 tensor-core causal flash attention.
// grid = (B*H, S/64); 128 threads = 4 warps, warp = 16 query rows.
// Q/K/V smem stride 72 halves; K/V double-buffered via cp.async.
// P accum -> A-frag is register-exact (half2 pairs), no shuffles.
// ---------------------------------------------------------------------------
#define AST 72

__global__ __launch_bounds__(128)
void attn_f16_kernel(const __half* __restrict__ qkv, __half* __restrict__ ctx)
{
    __shared__ __half Qs[64 * AST];
    __shared__ __half Ks[2][64 * AST];
    __shared__ __half Vs[2][64 * AST];

    const int bh = blockIdx.x;
    const int b  = bh / HH;
    const int h  = bh % HH;
    const int qt = gridDim.y - 1 - blockIdx.y;
    const int q0 = qt * 64;

    const int tid  = threadIdx.x;
    const int warp = tid >> 5;
    const int lane = tid & 31;
    const int gid  = lane >> 2;
    const int tig  = lane & 3;
    const int wr0  = warp * 16;

    #define ASTAGE(BUF, K0)                                                   \
        do {                                                                  \
            _Pragma("unroll")                                                 \
            for (int j = 0; j < 4; j++) {                                     \
                int idx = j * 128 + tid;                                      \
                int r = idx >> 3, c = idx & 7;                                \
                const __half* kp = qkv                                        \
                    + ((size_t)(b * SS + (K0) + r)) * (3 * DD)                \
                    + DD + h * HDIM + c * 8;                                  \
                cpa16(smem_u32(&Ks[BUF][r * AST + c * 8]), kp);               \
                cpa16(smem_u32(&Vs[BUF][r * AST + c * 8]), kp + DD);          \
            }                                                                 \
        } while (0)

    // stage tile 0 + load Q synchronously
    ASTAGE(0, 0);
    CP_COMMIT();
    #pragma unroll
    for (int j = 0; j < 4; j++) {
        int idx = j * 128 + tid;
        int r = idx >> 3, c = idx & 7;
        uint4 v = *reinterpret_cast<const uint4*>(
            qkv + ((size_t)(b * SS + q0 + r)) * (3 * DD) + h * HDIM + c * 8);
        *reinterpret_cast<uint4*>(&Qs[r * AST + c * 8]) = v;
    }
    __syncthreads();

    // Q a-frags (4 k16 steps over HDIM=64)
    const int i = lane;
    uint32_t qa[4][4];
    {
        uint32_t qbase = smem_u32(
            &Qs[(wr0 + (i & 7) + ((i >> 3) & 1) * 8) * AST + ((i >> 4) & 1) * 8]);
        #pragma unroll
        for (int ks = 0; ks < 4; ks++) ldsm_x4(qa[ks], qbase + ks * 32);
    }

    // lane bases for K (non-trans) and V (trans) fragments
    const int k_lrow = (i & 7) + ((i >> 4) & 1) * 8;   // key within 16-block
    const int k_ld   = ((i >> 3) & 1) * 8;             // d offset
    const int v_lrow = (i & 7) + ((i >> 3) & 1) * 8;   // key within 16-block
    const int v_ld   = ((i >> 4) & 1) * 8;             // d offset

    float oacc[8][4];
    #pragma unroll
    for (int a = 0; a < 8; a++)
        #pragma unroll
        for (int v = 0; v < 4; v++) oacc[a][v] = 0.f;
    float m0 = -1e30f, m1 = -1e30f, l0 = 0.f, l1 = 0.f;

    const int nt = q0 / 64 + 1;
    int buf = 0;
    for (int t = 0; t < nt; t++) {
        if (t + 1 < nt) {
            ASTAGE(buf ^ 1, (t + 1) * 64);
            CP_COMMIT();
            CP_WAIT(1);
        } else {
            CP_WAIT(0);
        }
        __syncthreads();

        const uint32_t kbase = smem_u32(&Ks[buf][k_lrow * AST + k_ld]);
        const uint32_t vbase = smem_u32(&Vs[buf][v_lrow * AST + v_ld]);

        // ---- S = Q K^T ----
        float sacc[8][4];
        #pragma unroll
        for (int ni = 0; ni < 8; ni++)
            sacc[ni][0] = sacc[ni][1] = sacc[ni][2] = sacc[ni][3] = 0.f;
        #pragma unroll
        for (int ks = 0; ks < 4; ks++) {
            #pragma unroll
            for (int kt = 0; kt < 4; kt++) {
                uint32_t kf[4];
                ldsm_x4(kf, kbase + (kt * 16 * AST + ks * 16) * 2);
                mma_f16(sacc[kt * 2 + 0], qa[ks], kf[0], kf[1]);
                mma_f16(sacc[kt * 2 + 1], qa[ks], kf[2], kf[3]);
            }
        }

        // ---- scale + causal mask (diagonal tile only) ----
        const bool diag = (t == nt - 1) && (q0 == t * 64);
        const int row_l0 = wr0 + gid;
        #pragma unroll
        for (int ni = 0; ni < 8; ni++) {
            #pragma unroll
            for (int v = 0; v < 4; v++) sacc[ni][v] *= 0.125f;
            if (diag) {
                int c = ni * 8 + 2 * tig;
                if (c     > row_l0)     sacc[ni][0] = -1e30f;
                if (c + 1 > row_l0)     sacc[ni][1] = -1e30f;
                if (c     > row_l0 + 8) sacc[ni][2] = -1e30f;
                if (c + 1 > row_l0 + 8) sacc[ni][3] = -1e30f;
            }
        }

        // ---- online softmax ----
        float tmax0 = -1e30f, tmax1 = -1e30f;
        #pragma unroll
        for (int ni = 0; ni < 8; ni++) {
            tmax0 = fmaxf(tmax0, fmaxf(sacc[ni][0], sacc[ni][1]));
            tmax1 = fmaxf(tmax1, fmaxf(sacc[ni][2], sacc[ni][3]));
        }
        tmax0 = fmaxf(tmax0, __shfl_xor_sync(0xffffffffu, tmax0, 1));
        tmax0 = fmaxf(tmax0, __shfl_xor_sync(0xffffffffu, tmax0, 2));
        tmax1 = fmaxf(tmax1, __shfl_xor_sync(0xffffffffu, tmax1, 1));
        tmax1 = fmaxf(tmax1, __shfl_xor_sync(0xffffffffu, tmax1, 2));

        float mn0 = fmaxf(m0, tmax0);
        float mn1 = fmaxf(m1, tmax1);
        float c0 = __expf(m0 - mn0);
        float c1 = __expf(m1 - mn1);
        m0 = mn0; m1 = mn1;

        float s0 = 0.f, s1 = 0.f;
        #pragma unroll
        for (int ni = 0; ni < 8; ni++) {
            sacc[ni][0] = __expf(sacc[ni][0] - mn0);
            sacc[ni][1] = __expf(sacc[ni][1] - mn0);
            sacc[ni][2] = __expf(sacc[ni][2] - mn1);
            sacc[ni][3] = __expf(sacc[ni][3] - mn1);
            s0 += sacc[ni][0] + sacc[ni][1];
            s1 += sacc[ni][2] + sacc[ni][3];
            oacc[ni][0] *= c0; oacc[ni][1] *= c0;
            oacc[ni][2] *= c1; oacc[ni][3] *= c1;
        }
        s0 += __shfl_xor_sync(0xffffffffu, s0, 1);
        s0 += __shfl_xor_sync(0xffffffffu, s0, 2);
        s1 += __shfl_xor_sync(0xffffffffu, s1, 1);
        s1 += __shfl_xor_sync(0xffffffffu, s1, 2);
        l0 = l0 * c0 + s0;
        l1 = l1 * c1 + s1;

        // ---- O += P V (P a-frags directly from accumulators) ----
        #pragma unroll
        for (int s = 0; s < 4; s++) {
            uint32_t pa[4];
            pa[0] = h2bits(sacc[2 * s][0],     sacc[2 * s][1]);
            pa[1] = h2bits(sacc[2 * s][2],     sacc[2 * s][3]);
            pa[2] = h2bits(sacc[2 * s + 1][0], sacc[2 * s + 1][1]);
            pa[3] = h2bits(sacc[2 * s + 1][2], sacc[2 * s + 1][3]);
            #pragma unroll
            for (int db = 0; db < 4; db++) {
                uint32_t vf[4];
                ldsm_x4t(vf, vbase + (s * 16 * AST + db * 16) * 2);
                mma_f16(oacc[db * 2 + 0], pa, vf[0], vf[1]);
                mma_f16(oacc[db * 2 + 1], pa, vf[2], vf[3]);
            }
        }
        __syncthreads();
        buf ^= 1;
    }

    // ---- normalize + write fp16 ctx ----
    float inv0 = 1.f / l0;
    float inv1 = 1.f / l1;
    int row0 = q0 + wr0 + gid;
    int row1 = row0 + 8;
    #pragma unroll
    for (int ni = 0; ni < 8; ni++) {
        int d = h * HDIM + ni * 8 + 2 * tig;
        __half2 h0 = __floats2half2_rn(oacc[ni][0] * inv0, oacc[ni][1] * inv0);
        __half2 h1 = __floats2half2_rn(oacc[ni][2] * inv1, oacc[ni][3] * inv1);
        *reinterpret_cast<__half2*>(&ctx[((size_t)(b * SS + row0)) * DD + d]) = h0;
        *reinterpret_cast<__half2*>(&ctx[((size_t)(b * SS + row1)) * DD + d]) = h1;
    }
}

// ---------------------------------------------------------------------------
// Launch
// ---------------------------------------------------------------------------
extern "C" void kernel_launch(void* const* d_in, const int* in_sizes, int n_in,
                              void* d_out, int out_size)
{
    const float* hidden = (const float*)d_in[0];
    const float* w_attn = (const float*)d_in[1];
    const float* b_attn = (const float*)d_in[2];
    const float* w_proj = (const float*)d_in[3];
    const float* b_proj = (const float*)d_in[4];
    float* out = (float*)d_out;

    __half *h16, *wa16, *wp16, *qkv16, *ctx16;
    cudaGetSymbolAddress((void**)&h16,   g_h16);
    cudaGetSymbolAddress((void**)&wa16,  g_wa16);
    cudaGetSymbolAddress((void**)&wp16,  g_wp16);
    cudaGetSymbolAddress((void**)&qkv16, g_qkv16);
    cudaGetSymbolAddress((void**)&ctx16, g_ctx16);

    const int M = BB * SS;   // 8192

    // 0) fp32 -> fp16 conversions
    {
        int n4 = BB * SS * DD / 4;
        f32_to_f16_kernel<<<(n4 + 255) / 256, 256>>>(
            (const float4*)hidden, (uint2*)h16, n4);
        n4 = DD * 3 * DD / 4;
        f32_to_f16_kernel<<<(n4 + 255) / 256, 256>>>(
            (const float4*)w_attn, (uint2*)wa16, n4);
        n4 = DD * DD / 4;
        f32_to_f16_kernel<<<(n4 + 255) / 256, 256>>>(
            (const float4*)w_proj, (uint2*)wp16, n4);
    }

    // 1) qkv16 = h16 @ wa16 + b_attn
    {
        dim3 grid(3 * DD / 128, M / 128);
        gemm_f16<1><<<grid, 256>>>(h16, wa16, b_attn, qkv16, M, 3 * DD, DD);
    }

    // 2) ctx16 = causal_attention(qkv16)
    {
        dim3 grid(BB * HH, SS / 64);
        attn_f16_kernel<<<grid, 128>>>(qkv16, ctx16);
    }

    // 3) out = ctx16 @ wp16 + b_proj (fp32 out)
    {
        dim3 grid(DD / 128, M / 128);
        gemm_f16<0><<<grid, 256>>>(ctx16, wp16, b_proj, out, M, DD, DD);
    }
}

// round 7
// speedup vs baseline: 8.9921x; 1.0079x over previous
#include <cuda_runtime.h>
#include <cuda_fp16.h>
#include <math.h>
#include <stdint.h>

#define BB 4
#define SS 2048
#define DD 1024
#define HH 16
#define HDIM 64

// fp16 scratch (device globals: allocation-free per harness rules)
__device__ __half g_h16[BB * SS * DD];
__device__ __half g_wa16[DD * 3 * DD];
__device__ __half g_wp16[DD * DD];
__device__ __half g_qkv16[BB * SS * 3 * DD];
__device__ __half g_ctx16[BB * SS * DD];

// ---------------------------------------------------------------------------
// helpers
// ---------------------------------------------------------------------------
__device__ __forceinline__ uint32_t smem_u32(const void* p) {
    uint32_t a;
    asm("{ .reg .u64 t; cvta.to.shared.u64 t, %1; cvt.u32.u64 %0, t; }"
        : "=r"(a) : "l"(p));
    return a;
}

__device__ __forceinline__ void cpa16(uint32_t dst, const void* src) {
    asm volatile("cp.async.ca.shared.global [%0], [%1], 16;"
                 :: "r"(dst), "l"(src));
}
#define CP_COMMIT() asm volatile("cp.async.commit_group;")
#define CP_WAIT(n)  asm volatile("cp.async.wait_group %0;" :: "n"(n))

__device__ __forceinline__ void ldsm_x4(uint32_t* d, uint32_t addr) {
    asm volatile("ldmatrix.sync.aligned.m8n8.x4.shared.b16 {%0,%1,%2,%3}, [%4];"
                 : "=r"(d[0]), "=r"(d[1]), "=r"(d[2]), "=r"(d[3]) : "r"(addr));
}
__device__ __forceinline__ void ldsm_x4t(uint32_t* d, uint32_t addr) {
    asm volatile("ldmatrix.sync.aligned.m8n8.x4.trans.shared.b16 {%0,%1,%2,%3}, [%4];"
                 : "=r"(d[0]), "=r"(d[1]), "=r"(d[2]), "=r"(d[3]) : "r"(addr));
}

__device__ __forceinline__ void mma_f16(float* c, const uint32_t* a,
                                        uint32_t b0, uint32_t b1) {
    asm volatile(
        "mma.sync.aligned.m16n8k16.row.col.f32.f16.f16.f32 "
        "{%0,%1,%2,%3}, {%4,%5,%6,%7}, {%8,%9}, {%0,%1,%2,%3};"
        : "+f"(c[0]), "+f"(c[1]), "+f"(c[2]), "+f"(c[3])
        : "r"(a[0]), "r"(a[1]), "r"(a[2]), "r"(a[3]), "r"(b0), "r"(b1));
}

__device__ __forceinline__ uint32_t h2bits(float x, float y) {
    __half2 h = __floats2half2_rn(x, y);
    return *reinterpret_cast<uint32_t*>(&h);
}

// ---------------------------------------------------------------------------
// fp32 -> fp16 conversion
// ---------------------------------------------------------------------------
__global__ void f32_to_f16_kernel(const float4* __restrict__ src,
                                  uint2* __restrict__ dst, int n4)
{
    int i = blockIdx.x * blockDim.x + threadIdx.x;
    if (i < n4) {
        float4 v = src[i];
        uint2 u;
        u.x = h2bits(v.x, v.y);
        u.y = h2bits(v.z, v.w);
        dst[i] = u;
    }
}

// ---------------------------------------------------------------------------
// fp16 GEMM v2: CTA 128x128, BK=64, 8 warps (4x2), warp 32x64,
// cp.async double-buffered, dynamic smem.
// ---------------------------------------------------------------------------
#define GLDA 72
#define GLDB 136
#define ABUF_B (128 * GLDA * 2)            // 18432
#define BBUF_B (64 * GLDB * 2)             // 17408
#define GSMEM_TOTAL (2 * ABUF_B + 2 * BBUF_B)  // 71680

template<int OUT16>
__global__ __launch_bounds__(256, 2)
void gemm_f16_v2(const __half* __restrict__ A, const __half* __restrict__ W,
                 const float* __restrict__ bias, void* __restrict__ Cout,
                 int M, int N, int K)
{
    extern __shared__ char gsm[];
    __half* As[2] = { (__half*)gsm, (__half*)(gsm + ABUF_B) };
    __half* Bs[2] = { (__half*)(gsm + 2 * ABUF_B),
                      (__half*)(gsm + 2 * ABUF_B + BBUF_B) };

    const int tid  = threadIdx.x;
    const int warp = tid >> 5;
    const int lane = tid & 31;
    const int gid  = lane >> 2;
    const int tig  = lane & 3;
    const int wm = warp >> 1;
    const int wn = warp & 1;

    const int row0 = blockIdx.y * 128;
    const int col0 = blockIdx.x * 128;

    float acc[2][8][4];
    #pragma unroll
    for (int a = 0; a < 2; a++)
        #pragma unroll
        for (int j = 0; j < 8; j++)
            #pragma unroll
            for (int v = 0; v < 4; v++) acc[a][j][v] = 0.f;

    #define GSTAGE(BUF, KT)                                                   \
        do {                                                                  \
            _Pragma("unroll")                                                 \
            for (int j = 0; j < 4; j++) {                                     \
                int idx = j * 256 + tid;                                      \
                int r = idx >> 3, c = idx & 7;                                \
                cpa16(smem_u32(&As[BUF][r * GLDA + c * 8]),                   \
                      A + (size_t)(row0 + r) * K + (KT) * 64 + c * 8);        \
            }                                                                 \
            _Pragma("unroll")                                                 \
            for (int j = 0; j < 4; j++) {                                     \
                int idx = j * 256 + tid;                                      \
                int kr = idx >> 4, c = idx & 15;                              \
                cpa16(smem_u32(&Bs[BUF][kr * GLDB + c * 8]),                  \
                      W + (size_t)((KT) * 64 + kr) * N + col0 + c * 8);       \
            }                                                                 \
        } while (0)

    const int i = lane;
    const int a_lrow = wm * 32 + (i & 7) + ((i >> 3) & 1) * 8;
    const int a_lk   = ((i >> 4) & 1) * 8;
    const int b_lk   = (i & 7) + ((i >> 3) & 1) * 8;
    const int b_lc   = wn * 64 + ((i >> 4) & 1) * 8;

    GSTAGE(0, 0);
    CP_COMMIT();

    const int NT = K / 64;
    int buf = 0;
    for (int t = 0; t < NT; t++) {
        if (t + 1 < NT) {
            GSTAGE(buf ^ 1, t + 1);
            CP_COMMIT();
            CP_WAIT(1);
        } else {
            CP_WAIT(0);
        }
        __syncthreads();

        const uint32_t abase = smem_u32(&As[buf][a_lrow * GLDA + a_lk]);
        const uint32_t bbase = smem_u32(&Bs[buf][b_lk * GLDB + b_lc]);
        #pragma unroll
        for (int ks = 0; ks < 4; ks++) {
            uint32_t af[2][4];
            ldsm_x4(af[0], abase + ks * 32);
            ldsm_x4(af[1], abase + 16 * GLDA * 2 + ks * 32);
            uint32_t bf[4][4];
            #pragma unroll
            for (int nb = 0; nb < 4; nb++)
                ldsm_x4t(bf[nb], bbase + (ks * 16 * GLDB + nb * 16) * 2);
            #pragma unroll
            for (int nb = 0; nb < 4; nb++)
                #pragma unroll
                for (int hn = 0; hn < 2; hn++) {
                    int ni = nb * 2 + hn;
                    mma_f16(acc[0][ni], af[0], bf[nb][hn * 2], bf[nb][hn * 2 + 1]);
                    mma_f16(acc[1][ni], af[1], bf[nb][hn * 2], bf[nb][hn * 2 + 1]);
                }
        }
        __syncthreads();
        buf ^= 1;
    }

    #pragma unroll
    for (int mi = 0; mi < 2; mi++) {
        int r = row0 + wm * 32 + mi * 16 + gid;
        #pragma unroll
        for (int ni = 0; ni < 8; ni++) {
            int c = col0 + wn * 64 + ni * 8 + 2 * tig;
            float bx = __ldg(&bias[c]);
            float by = __ldg(&bias[c + 1]);
            if (OUT16) {
                __half* C16 = (__half*)Cout;
                __half2 h0 = __floats2half2_rn(acc[mi][ni][0] + bx,
                                               acc[mi][ni][1] + by);
                __half2 h1 = __floats2half2_rn(acc[mi][ni][2] + bx,
                                               acc[mi][ni][3] + by);
                *reinterpret_cast<__half2*>(&C16[(size_t)r * N + c]) = h0;
                *reinterpret_cast<__half2*>(&C16[(size_t)(r + 8) * N + c]) = h1;
            } else {
                float* C32 = (float*)Cout;
                float2 o0 = make_float2(acc[mi][ni][0] + bx, acc[mi][ni][1] + by);
                float2 o1 = make_float2(acc[mi][ni][2] + bx, acc[mi][ni][3] + by);
                *reinterpret_cast<float2*>(&C32[(size_t)r * N + c]) = o0;
                *reinterpret_cast<float2*>(&C32[(size_t)(r + 8) * N + c]) = o1;
            }
        }
    }
}

// ---------------------------------------------------------------------------
// fp16 flash attention v2: 128 queries/CTA, 8 warps (16 rows each),
// 64-key tiles double-buffered via cp.async, dynamic smem.
// ---------------------------------------------------------------------------
#define AST 72
#define Q_BYTES (128 * AST * 2)            // 18432
#define KV_BYTES (64 * AST * 2)            // 9216
#define ASMEM_TOTAL (Q_BYTES + 4 * KV_BYTES)   // 55296

__global__ __launch_bounds__(256)
void attn_f16_v2(const __half* __restrict__ qkv, __half* __restrict__ ctx)
{
    extern __shared__ char smraw[];
    __half* Qs = (__half*)smraw;
    __half* Ks[2] = { (__half*)(smraw + Q_BYTES),
                      (__half*)(smraw + Q_BYTES + KV_BYTES) };
    __half* Vs[2] = { (__half*)(smraw + Q_BYTES + 2 * KV_BYTES),
                      (__half*)(smraw + Q_BYTES + 3 * KV_BYTES) };

    const int bh = blockIdx.x;
    const int b  = bh / HH;
    const int h  = bh % HH;
    const int qt = gridDim.y - 1 - blockIdx.y;   // long CTAs first
    const int q0 = qt * 128;

    const int tid  = threadIdx.x;
    const int warp = tid >> 5;
    const int lane = tid & 31;
    const int gid  = lane >> 2;
    const int tig  = lane & 3;
    const int wr0  = warp * 16;

    #define ASTAGE(BUF, K0)                                                   \
        do {                                                                  \
            _Pragma("unroll")                                                 \
            for (int j = 0; j < 2; j++) {                                     \
                int idx = j * 256 + tid;                                      \
                int r = idx >> 3, c = idx & 7;                                \
                const __half* kp = qkv                                        \
                    + ((size_t)(b * SS + (K0) + r)) * (3 * DD)                \
                    + DD + h * HDIM + c * 8;                                  \
                cpa16(smem_u32(&Ks[BUF][r * AST + c * 8]), kp);               \
                cpa16(smem_u32(&Vs[BUF][r * AST + c * 8]), kp + DD);          \
            }                                                                 \
        } while (0)

    ASTAGE(0, 0);
    CP_COMMIT();
    #pragma unroll
    for (int j = 0; j < 4; j++) {
        int idx = j * 256 + tid;
        int r = idx >> 3, c = idx & 7;
        uint4 v = *reinterpret_cast<const uint4*>(
            qkv + ((size_t)(b * SS + q0 + r)) * (3 * DD) + h * HDIM + c * 8);
        *reinterpret_cast<uint4*>(&Qs[r * AST + c * 8]) = v;
    }
    __syncthreads();

    const int i = lane;
    uint32_t qa[4][4];
    {
        uint32_t qbase = smem_u32(
            &Qs[(wr0 + (i & 7) + ((i >> 3) & 1) * 8) * AST + ((i >> 4) & 1) * 8]);
        #pragma unroll
        for (int ks = 0; ks < 4; ks++) ldsm_x4(qa[ks], qbase + ks * 32);
    }

    const int k_lrow = (i & 7) + ((i >> 4) & 1) * 8;
    const int k_ld   = ((i >> 3) & 1) * 8;
    const int v_lrow = (i & 7) + ((i >> 3) & 1) * 8;
    const int v_ld   = ((i >> 4) & 1) * 8;

    float oacc[8][4];
    #pragma unroll
    for (int a = 0; a < 8; a++)
        #pragma unroll
        for (int v = 0; v < 4; v++) oacc[a][v] = 0.f;
    float m0 = -1e30f, m1 = -1e30f, l0 = 0.f, l1 = 0.f;

    const int nt = q0 / 64 + 2;
    const int warp_maxrow = q0 + wr0 + 15;
    int buf = 0;
    for (int t = 0; t < nt; t++) {
        const int k0 = t * 64;
        if (t + 1 < nt) {
            ASTAGE(buf ^ 1, (t + 1) * 64);
            CP_COMMIT();
            CP_WAIT(1);
        } else {
            CP_WAIT(0);
        }
        __syncthreads();

        if (k0 <= warp_maxrow) {   // warp has at least one unmasked key
            const uint32_t kbase = smem_u32(&Ks[buf][k_lrow * AST + k_ld]);
            const uint32_t vbase = smem_u32(&Vs[buf][v_lrow * AST + v_ld]);

            // ---- S = Q K^T ----
            float sacc[8][4];
            #pragma unroll
            for (int ni = 0; ni < 8; ni++)
                sacc[ni][0] = sacc[ni][1] = sacc[ni][2] = sacc[ni][3] = 0.f;
            #pragma unroll
            for (int ks = 0; ks < 4; ks++) {
                #pragma unroll
                for (int kt = 0; kt < 4; kt++) {
                    uint32_t kf[4];
                    ldsm_x4(kf, kbase + (kt * 16 * AST + ks * 16) * 2);
                    mma_f16(sacc[kt * 2 + 0], qa[ks], kf[0], kf[1]);
                    mma_f16(sacc[kt * 2 + 1], qa[ks], kf[2], kf[3]);
                }
            }

            // ---- scale + causal mask (only near-diagonal tiles) ----
            const int rg0 = q0 + wr0 + gid;       // this lane's row (and +8)
            const bool need_mask = (k0 + 63 > q0 + wr0);
            #pragma unroll
            for (int ni = 0; ni < 8; ni++) {
                #pragma unroll
                for (int v = 0; v < 4; v++) sacc[ni][v] *= 0.125f;
                if (need_mask) {
                    int cg = k0 + ni * 8 + 2 * tig;
                    if (cg     > rg0)     sacc[ni][0] = -1e30f;
                    if (cg + 1 > rg0)     sacc[ni][1] = -1e30f;
                    if (cg     > rg0 + 8) sacc[ni][2] = -1e30f;
                    if (cg + 1 > rg0 + 8) sacc[ni][3] = -1e30f;
                }
            }

            // ---- online softmax ----
            float tmax0 = -1e30f, tmax1 = -1e30f;
            #pragma unroll
            for (int ni = 0; ni < 8; ni++) {
                tmax0 = fmaxf(tmax0, fmaxf(sacc[ni][0], sacc[ni][1]));
                tmax1 = fmaxf(tmax1, fmaxf(sacc[ni][2], sacc[ni][3]));
            }
            tmax0 = fmaxf(tmax0, __shfl_xor_sync(0xffffffffu, tmax0, 1));
            tmax0 = fmaxf(tmax0, __shfl_xor_sync(0xffffffffu, tmax0, 2));
            tmax1 = fmaxf(tmax1, __shfl_xor_sync(0xffffffffu, tmax1, 1));
            tmax1 = fmaxf(tmax1, __shfl_xor_sync(0xffffffffu, tmax1, 2));

            float mn0 = fmaxf(m0, tmax0);
            float mn1 = fmaxf(m1, tmax1);
            float c0 = __expf(m0 - mn0);
            float c1 = __expf(m1 - mn1);
            m0 = mn0; m1 = mn1;

            float s0 = 0.f, s1 = 0.f;
            #pragma unroll
            for (int ni = 0; ni < 8; ni++) {
                sacc[ni][0] = __expf(sacc[ni][0] - mn0);
                sacc[ni][1] = __expf(sacc[ni][1] - mn0);
                sacc[ni][2] = __expf(sacc[ni][2] - mn1);
                sacc[ni][3] = __expf(sacc[ni][3] - mn1);
                s0 += sacc[ni][0] + sacc[ni][1];
                s1 += sacc[ni][2] + sacc[ni][3];
                oacc[ni][0] *= c0; oacc[ni][1] *= c0;
                oacc[ni][2] *= c1; oacc[ni][3] *= c1;
            }
            s0 += __shfl_xor_sync(0xffffffffu, s0, 1);
            s0 += __shfl_xor_sync(0xffffffffu, s0, 2);
            s1 += __shfl_xor_sync(0xffffffffu, s1, 1);
            s1 += __shfl_xor_sync(0xffffffffu, s1, 2);
            l0 = l0 * c0 + s0;
            l1 = l1 * c1 + s1;

            // ---- O += P V ----
            #pragma unroll
            for (int s = 0; s < 4; s++) {
                uint32_t pa[4];
                pa[0] = h2bits(sacc[2 * s][0],     sacc[2 * s][1]);
                pa[1] = h2bits(sacc[2 * s][2],     sacc[2 * s][3]);
                pa[2] = h2bits(sacc[2 * s + 1][0], sacc[2 * s + 1][1]);
                pa[3] = h2bits(sacc[2 * s + 1][2], sacc[2 * s + 1][3]);
                #pragma unroll
                for (int db = 0; db < 4; db++) {
                    uint32_t vf[4];
                    ldsm_x4t(vf, vbase + (s * 16 * AST + db * 16) * 2);
                    mma_f16(oacc[db * 2 + 0], pa, vf[0], vf[1]);
                    mma_f16(oacc[db * 2 + 1], pa, vf[2], vf[3]);
                }
            }
        }
        __syncthreads();
        buf ^= 1;
    }

    float inv0 = 1.f / l0;
    float inv1 = 1.f / l1;
    int row0 = q0 + wr0 + gid;
    int row1 = row0 + 8;
    #pragma unroll
    for (int ni = 0; ni < 8; ni++) {
        int d = h * HDIM + ni * 8 + 2 * tig;
        __half2 h0 = __floats2half2_rn(oacc[ni][0] * inv0, oacc[ni][1] * inv0);
        __half2 h1 = __floats2half2_rn(oacc[ni][2] * inv1, oacc[ni][3] * inv1);
        *reinterpret_cast<__half2*>(&ctx[((size_t)(b * SS + row0)) * DD + d]) = h0;
        *reinterpret_cast<__half2*>(&ctx[((size_t)(b * SS + row1)) * DD + d]) = h1;
    }
}

// ---------------------------------------------------------------------------
// Launch
// ---------------------------------------------------------------------------
extern "C" void kernel_launch(void* const* d_in, const int* in_sizes, int n_in,
                              void* d_out, int out_size)
{
    const float* hidden = (const float*)d_in[0];
    const float* w_attn = (const float*)d_in[1];
    const float* b_attn = (const float*)d_in[2];
    const float* w_proj = (const float*)d_in[3];
    const float* b_proj = (const float*)d_in[4];
    float* out = (float*)d_out;

    __half *h16, *wa16, *wp16, *qkv16, *ctx16;
    cudaGetSymbolAddress((void**)&h16,   g_h16);
    cudaGetSymbolAddress((void**)&wa16,  g_wa16);
    cudaGetSymbolAddress((void**)&wp16,  g_wp16);
    cudaGetSymbolAddress((void**)&qkv16, g_qkv16);
    cudaGetSymbolAddress((void**)&ctx16, g_ctx16);

    static bool attr_done = false;
    if (!attr_done) {
        cudaFuncSetAttribute(gemm_f16_v2<1>,
                             cudaFuncAttributeMaxDynamicSharedMemorySize,
                             GSMEM_TOTAL);
        cudaFuncSetAttribute(gemm_f16_v2<0>,
                             cudaFuncAttributeMaxDynamicSharedMemorySize,
                             GSMEM_TOTAL);
        cudaFuncSetAttribute(attn_f16_v2,
                             cudaFuncAttributeMaxDynamicSharedMemorySize,
                             ASMEM_TOTAL);
        attr_done = true;
    }

    const int M = BB * SS;   // 8192

    // 0) fp32 -> fp16 conversions
    {
        int n4 = BB * SS * DD / 4;
        f32_to_f16_kernel<<<(n4 + 255) / 256, 256>>>(
            (const float4*)hidden, (uint2*)h16, n4);
        n4 = DD * 3 * DD / 4;
        f32_to_f16_kernel<<<(n4 + 255) / 256, 256>>>(
            (const float4*)w_attn, (uint2*)wa16, n4);
        n4 = DD * DD / 4;
        f32_to_f16_kernel<<<(n4 + 255) / 256, 256>>>(
            (const float4*)w_proj, (uint2*)wp16, n4);
    }

    // 1) qkv16 = h16 @ wa16 + b_attn
    {
        dim3 grid(3 * DD / 128, M / 128);
        gemm_f16_v2<1><<<grid, 256, GSMEM_TOTAL>>>(h16, wa16, b_attn, qkv16,
                                                   M, 3 * DD, DD);
    }

    // 2) ctx16 = causal_attention(qkv16)
    {
        dim3 grid(BB * HH, SS / 128);
        attn_f16_v2<<<grid, 256, ASMEM_TOTAL>>>(qkv16, ctx16);
    }

    // 3) out = ctx16 @ wp16 + b_proj (fp32 out)
    {
        dim3 grid(DD / 128, M / 128);
        gemm_f16_v2<0><<<grid, 256, GSMEM_TOTAL>>>(ctx16, wp16, b_proj, out,
                                                   M, DD, DD);
    }
}